// round 8
// baseline (speedup 1.0000x reference)
#include <cuda_runtime.h>
#include <cstdint>

#define SQ 2048
#define DM 1024
#define NH 16
#define HD 64
#define NT (SQ / 64)  // 32 column tiles in fused

// Scratch (allocation-free)
__device__ uint32_t g_mbits[64 * SQ];        // mask bitmask, [wordcol][row]
__device__ uint32_t g_ap[3 * 512 * 4096];    // q,k,v inputs: permuted [z][mt][kt] tiles
__device__ uint32_t g_wp[4 * 256 * 4096];    // Wq,Wk,Wv,Wo: permuted [w][nt][kt] tiles
__device__ uint32_t g_op[512 * 4096];        // attention out O: permuted [mt][kt] tiles
__device__ uint32_t g_qp[NH * 16 * 8192];    // Q proj (pre-scaled by 1/8), per (h, mtile)
__device__ uint32_t g_kp[NH * 32 * 4096];    // K proj, permuted per (h, ttile)
__device__ uint32_t g_vp[NH * 32 * 4096];    // V^T proj, permuted per (h, ttile)

__device__ __forceinline__ uint32_t f2tf(float f) {
    uint32_t u;
    asm("cvt.rna.tf32.f32 %0, %1;" : "=r"(u) : "f"(f));
    return u;
}

__device__ __forceinline__ void mma8(float* c, uint32_t a0, uint32_t a1, uint32_t a2,
                                     uint32_t a3, uint32_t b0, uint32_t b1) {
    asm("mma.sync.aligned.m16n8k8.row.col.f32.tf32.tf32.f32 "
        "{%0,%1,%2,%3},{%4,%5,%6,%7},{%8,%9},{%0,%1,%2,%3};"
        : "+f"(c[0]), "+f"(c[1]), "+f"(c[2]), "+f"(c[3])
        : "r"(a0), "r"(a1), "r"(a2), "r"(a3), "r"(b0), "r"(b1));
}

// Permuted fragment-major layout (one LDS.128 per mma fragment).
__device__ __forceinline__ int perm_word(int NS, int r, int k) {
    int gg = r & 7;
    int kk = k & 7;
    int L = gg * 4 + ((kk & 3) ^ (gg & 3));
    return (((r >> 4) * NS + (k >> 3)) * 32 + L) * 4 + ((r >> 3) & 1) + 2 * (kk >> 2);
}
__device__ __forceinline__ void sts_perm4(uint32_t* S, int NS, int r, int c4, uint4 u) {
    int gg = r & 7;
    int base = (((r >> 4) * NS + (c4 >> 3)) * 32 + gg * 4) * 4 + ((r >> 3) & 1) +
               2 * ((c4 >> 2) & 1);
    int x = gg & 3;
    S[base + (0 ^ x) * 4] = u.x;
    S[base + (1 ^ x) * 4] = u.y;
    S[base + (2 ^ x) * 4] = u.z;
    S[base + (3 ^ x) * 4] = u.w;
}
__device__ __forceinline__ int frag_addr(int NS, int band, int s, int g, int t4) {
    return ((band * NS + s) * 32 + g * 4 + (t4 ^ (g & 3))) * 4;
}

__device__ __forceinline__ void cpa16(void* dst, const void* src) {
    uint32_t s = (uint32_t)__cvta_generic_to_shared(dst);
    asm volatile("cp.async.cg.shared.global [%0], [%1], 16;" ::"r"(s), "l"(src));
}
#define CPA_COMMIT asm volatile("cp.async.commit_group;")
#define CPA_WAIT(n) asm volatile("cp.async.wait_group %0;" ::"n"(n))

// ---------------------------------------------------------------------------
// Pre-pass: tf32-round + pre-permute activations (blocks 0..1535) and weights
// (1536..2559); mask bit-compaction (2560+).
// ---------------------------------------------------------------------------
__global__ __launch_bounds__(256) void prep(
    const float* __restrict__ q_in, const float* __restrict__ k_in,
    const float* __restrict__ v_in, const float* __restrict__ Wq,
    const float* __restrict__ Wk, const float* __restrict__ Wv,
    const float* __restrict__ Wo, const int* __restrict__ mask) {
    const int bid = blockIdx.x;
    const int tid = threadIdx.x;

    if (bid >= 2560) {  // mask compaction: 256 blocks x 8 rows (warp per row)
        const int lane = tid & 31, wid = tid >> 5;
        const int row = (bid - 2560) * 8 + wid;
        const int4* mp = (const int4*)(mask + (size_t)row * SQ + lane * 64);
        uint32_t w0 = 0, w1 = 0;
#pragma unroll
        for (int i = 0; i < 16; i++) {
            int4 m = mp[i];
            uint32_t bits = (m.x != 0 ? 1u : 0u) | (m.y != 0 ? 2u : 0u) |
                            (m.z != 0 ? 4u : 0u) | (m.w != 0 ? 8u : 0u);
            if (i < 8)
                w0 |= bits << (i * 4);
            else
                w1 |= bits << ((i - 8) * 4);
        }
        g_mbits[(lane * 2 + 0) * SQ + row] = w0;
        g_mbits[(lane * 2 + 1) * SQ + row] = w1;
        return;
    }

    __shared__ uint32_t sp[4096];
    const float* src;
    uint32_t* dst;
    int r0, c0;
    if (bid < 1536) {  // activation tile: z, mt(16), kt(32)
        int z = bid >> 9, rem = bid & 511;
        src = z == 0 ? q_in : z == 1 ? k_in : v_in;
        r0 = (rem >> 5) * 128;
        c0 = (rem & 31) * 32;
        dst = g_ap + bid * 4096;
    } else {  // weight tile: w(4), nt(8), kt(32)
        int wb = bid - 1536;
        int w = wb >> 8, rem = wb & 255;
        src = w == 0 ? Wq : w == 1 ? Wk : w == 2 ? Wv : Wo;
        r0 = (rem >> 5) * 128;
        c0 = (rem & 31) * 32;
        dst = g_wp + wb * 4096;
    }
#pragma unroll
    for (int i = 0; i < 4; i++) {
        int idx = tid + i * 256, r = idx >> 3, c4 = (idx & 7) * 4;
        float4 v = *(const float4*)(src + (size_t)(r0 + r) * DM + c0 + c4);
        uint4 u = {f2tf(v.x), f2tf(v.y), f2tf(v.z), f2tf(v.w)};
        sts_perm4(sp, 4, r, c4, u);
    }
    __syncthreads();
#pragma unroll
    for (int i = 0; i < 4; i++)
        *(uint4*)(dst + tid * 4 + i * 1024) = *(const uint4*)(sp + tid * 4 + i * 1024);
}

// ---------------------------------------------------------------------------
// QKV projection GEMMs from pre-permuted tiles. cp.async double-buffered.
// Q epilogue pre-scales by 1/8 (power of two -> bit-exact vs scaling later).
// ---------------------------------------------------------------------------
__global__ __launch_bounds__(256, 2) void gemm_qkv() {
    extern __shared__ uint32_t sm[];  // 2 stages x (A 4096 | B 4096)
    const int z = blockIdx.z, mt = blockIdx.y, nt = blockIdx.x;
    const int tid = threadIdx.x, lane = tid & 31, wid = tid >> 5;
    const int g = lane >> 2, t4 = lane & 3;
    const int wm = (wid & 1) * 64, wn = (wid >> 1) * 32;
    const uint32_t* At = g_ap + (size_t)(z * 512 + mt * 32) * 4096;
    const uint32_t* Bt = g_wp + (size_t)(z * 256 + nt * 32) * 4096;

#pragma unroll
    for (int i = 0; i < 4; i++) {
        cpa16(sm + tid * 4 + i * 1024, At + tid * 4 + i * 1024);
        cpa16(sm + 4096 + tid * 4 + i * 1024, Bt + tid * 4 + i * 1024);
    }
    CPA_COMMIT;

    float acc[4][4][4] = {};

    for (int kt = 0; kt < 32; kt++) {
        uint32_t* S = sm + (kt & 1) * 8192;
        CPA_WAIT(0);
        __syncthreads();
        if (kt + 1 < 32) {
            uint32_t* Nx = sm + ((kt + 1) & 1) * 8192;
            const uint32_t* An = At + (kt + 1) * 4096;
            const uint32_t* Bn = Bt + (kt + 1) * 4096;
#pragma unroll
            for (int i = 0; i < 4; i++) {
                cpa16(Nx + tid * 4 + i * 1024, An + tid * 4 + i * 1024);
                cpa16(Nx + 4096 + tid * 4 + i * 1024, Bn + tid * 4 + i * 1024);
            }
            CPA_COMMIT;
        }
#pragma unroll
        for (int s = 0; s < 4; s++) {
            uint4 av[4], bv[2];
#pragma unroll
            for (int mi = 0; mi < 4; mi++)
                av[mi] = *(const uint4*)&S[frag_addr(4, (wm >> 4) + mi, s, g, t4)];
#pragma unroll
            for (int bi = 0; bi < 2; bi++)
                bv[bi] = *(const uint4*)&S[4096 + frag_addr(4, (wn >> 4) + bi, s, g, t4)];
#pragma unroll
            for (int mi = 0; mi < 4; mi++)
#pragma unroll
                for (int bi = 0; bi < 2; bi++) {
                    mma8(acc[mi][bi * 2], av[mi].x, av[mi].y, av[mi].z, av[mi].w,
                         bv[bi].x, bv[bi].z);
                    mma8(acc[mi][bi * 2 + 1], av[mi].x, av[mi].y, av[mi].z, av[mi].w,
                         bv[bi].y, bv[bi].w);
                }
        }
    }

    // epilogue: tf32-round, write per-head permuted layouts (Q scaled by 1/8)
#pragma unroll
    for (int mi = 0; mi < 4; mi++)
#pragma unroll
        for (int ni = 0; ni < 4; ni++)
#pragma unroll
            for (int e = 0; e < 4; e++) {
                int row = wm + mi * 16 + g + ((e >> 1) * 8);  // 0..127
                int col = wn + ni * 8 + t4 * 2 + (e & 1);     // 0..127
                int gn = nt * 128 + col;
                int h = gn >> 6, c64 = gn & 63;
                if (z == 0) {
                    g_qp[(h * 16 + mt) * 8192 + perm_word(8, row, c64)] =
                        f2tf(acc[mi][ni][e] * 0.125f);
                } else {
                    uint32_t val = f2tf(acc[mi][ni][e]);
                    int tile = mt * 2 + (row >> 6);
                    int r64 = row & 63;
                    if (z == 1)
                        g_kp[(h * 32 + tile) * 4096 + perm_word(8, r64, c64)] = val;
                    else
                        g_vp[(h * 32 + tile) * 4096 + perm_word(8, c64, r64)] = val;
                }
            }
}

// ---------------------------------------------------------------------------
// Fused attention: S = (Q/8)K^T, masked -> write pre-softmax v to attn (raw),
// stage tf32(v) to Sp, O += S@V. No exp, no reductions (moved to tail).
// ---------------------------------------------------------------------------
__global__ __launch_bounds__(256, 2) void fused_attn(float* __restrict__ attn) {
    extern __shared__ uint32_t sm[];
    uint32_t* Qp = sm;            // 8192 w
    uint32_t* Kp = sm + 8192;     // 2 x 4096 w
    uint32_t* Vp = sm + 16384;    // 4096 w
    uint32_t* Sp = sm + 20480;    // 8192 w

    const int tid = threadIdx.x, lane = tid & 31, wid = tid >> 5;
    const int g = lane >> 2, t4 = lane & 3;
    const int wm = (wid & 1) * 64, wn = (wid >> 1) * 16;
    const int h = blockIdx.y, mt = blockIdx.x;
    const int m0 = mt * 128;
    const int slot = wn >> 5;
    const size_t attn_base = (size_t)h * SQ * SQ;
    const uint32_t* kg = g_kp + h * 32 * 4096;
    const uint32_t* vg = g_vp + h * 32 * 4096;

    // prologue: cp.async K[0] and Q
#pragma unroll
    for (int i = 0; i < 4; i++)
        cpa16(Kp + tid * 4 + i * 1024, kg + tid * 4 + i * 1024);
    {
        const uint32_t* qg = g_qp + (h * 16 + mt) * 8192;
#pragma unroll
        for (int i = 0; i < 8; i++)
            cpa16(Qp + tid * 4 + i * 1024, qg + tid * 4 + i * 1024);
    }
    CPA_COMMIT;

    float oacc[4][2][4] = {};

    for (int tt = 0; tt < NT; tt++) {
        const int t0 = tt * 64;
        uint32_t* Kc = Kp + (tt & 1) * 4096;

        CPA_WAIT(0);
        __syncthreads();

        uint32_t mw[4][2];
        {
            const uint32_t* mb = g_mbits + (tt * 2 + slot) * SQ + m0;
#pragma unroll
            for (int mi = 0; mi < 4; mi++)
#pragma unroll
                for (int e2 = 0; e2 < 2; e2++)
                    mw[mi][e2] = mb[wm + mi * 16 + g + e2 * 8];
        }

#pragma unroll
        for (int i = 0; i < 4; i++)
            cpa16(Vp + tid * 4 + i * 1024, vg + tt * 4096 + tid * 4 + i * 1024);
        CPA_COMMIT;
        if (tt + 1 < NT) {
            uint32_t* Kn = Kp + ((tt + 1) & 1) * 4096;
#pragma unroll
            for (int i = 0; i < 4; i++)
                cpa16(Kn + tid * 4 + i * 1024, kg + (tt + 1) * 4096 + tid * 4 + i * 1024);
        }
        CPA_COMMIT;

        // S = (Q/8) K^T  (scale folded into Q)
        float sacc[4][2][4] = {};
#pragma unroll
        for (int s = 0; s < 8; s++) {
            uint4 aq[4];
#pragma unroll
            for (int mi = 0; mi < 4; mi++)
                aq[mi] = *(const uint4*)&Qp[frag_addr(8, (wm >> 4) + mi, s, g, t4)];
            uint4 bk = *(const uint4*)&Kc[frag_addr(8, wn >> 4, s, g, t4)];
#pragma unroll
            for (int mi = 0; mi < 4; mi++) {
                mma8(sacc[mi][0], aq[mi].x, aq[mi].y, aq[mi].z, aq[mi].w, bk.x, bk.z);
                mma8(sacc[mi][1], aq[mi].x, aq[mi].y, aq[mi].z, aq[mi].w, bk.y, bk.w);
            }
        }

        // epilogue: mask; attn <- v (pre-softmax, streaming); Sp <- tf32(v)
#pragma unroll
        for (int mi = 0; mi < 4; mi++)
#pragma unroll
            for (int ni = 0; ni < 2; ni++)
#pragma unroll
                for (int e2 = 0; e2 < 2; e2++) {
                    int rl = wm + mi * 16 + g + e2 * 8;
                    int cl = wn + ni * 8 + t4 * 2;
                    int rg = m0 + rl, cg = t0 + cl;
                    float v0 = sacc[mi][ni][e2 * 2];
                    float v1 = sacc[mi][ni][e2 * 2 + 1];
                    uint32_t w = mw[mi][e2];
                    if ((w >> (cl & 31)) & 1) v0 = -1e-7f;
                    if ((w >> ((cl & 31) + 1)) & 1) v1 = -1e-7f;
                    __stcs((float2*)(attn + attn_base + (size_t)rg * SQ + cg),
                           make_float2(v0, v1));
                    Sp[perm_word(8, rl, cl)] = f2tf(v0);
                    Sp[perm_word(8, rl, cl + 1)] = f2tf(v1);
                }

        CPA_WAIT(1);
        __syncthreads();

        // O += S @ V
#pragma unroll
        for (int s = 0; s < 8; s++) {
            uint4 as[4];
#pragma unroll
            for (int mi = 0; mi < 4; mi++)
                as[mi] = *(const uint4*)&Sp[frag_addr(8, (wm >> 4) + mi, s, g, t4)];
            uint4 bv = *(const uint4*)&Vp[frag_addr(8, wn >> 4, s, g, t4)];
#pragma unroll
            for (int mi = 0; mi < 4; mi++) {
                mma8(oacc[mi][0], as[mi].x, as[mi].y, as[mi].z, as[mi].w, bv.x, bv.z);
                mma8(oacc[mi][1], as[mi].x, as[mi].y, as[mi].z, as[mi].w, bv.y, bv.w);
            }
        }
    }

    // O epilogue: tf32-round + permuted tile write for output GEMM
#pragma unroll
    for (int mi = 0; mi < 4; mi++)
#pragma unroll
        for (int ni = 0; ni < 2; ni++)
#pragma unroll
            for (int e = 0; e < 4; e++) {
                int rl = wm + mi * 16 + g + (e >> 1) * 8;
                int col = wn + ni * 8 + t4 * 2 + (e & 1);  // 0..63
                int kt = h * 2 + (col >> 5);
                g_op[(mt * 32 + kt) * 4096 + perm_word(4, rl, col & 31)] =
                    f2tf(oacc[mi][ni][e]);
            }
}

// ---------------------------------------------------------------------------
// Heterogeneous tail: blocks 0..127 = output projection (cp.async GEMM);
// blocks 128+ = one-pass row softmax (read v, exp, block-sum, scale, write).
// 2 rows per iteration, parity-alternating reduction slots (1 sync/iter).
// ---------------------------------------------------------------------------
__global__ __launch_bounds__(256, 2) void out_softmax(float* __restrict__ C,
                                                      float* __restrict__ attn) {
    extern __shared__ uint32_t sm[];
    const int bid = blockIdx.x;
    const int tid = threadIdx.x;

    if (bid >= 128) {  // softmax: 2048 blocks x 16 rows
        float* red = (float*)sm;  // [2 parity][8 warps][2 rows]
        const int lane = tid & 31, wid = tid >> 5;
        const int r0 = (bid - 128) * 16;
        for (int rr = 0; rr < 16; rr += 2) {
            float* p0 = attn + (size_t)(r0 + rr) * SQ;
            float* p1 = p0 + SQ;
            float4 a0 = __ldcs((const float4*)(p0 + tid * 4));
            float4 b0 = __ldcs((const float4*)(p0 + 1024 + tid * 4));
            float4 a1 = __ldcs((const float4*)(p1 + tid * 4));
            float4 b1 = __ldcs((const float4*)(p1 + 1024 + tid * 4));
            a0.x = __expf(a0.x); a0.y = __expf(a0.y);
            a0.z = __expf(a0.z); a0.w = __expf(a0.w);
            b0.x = __expf(b0.x); b0.y = __expf(b0.y);
            b0.z = __expf(b0.z); b0.w = __expf(b0.w);
            a1.x = __expf(a1.x); a1.y = __expf(a1.y);
            a1.z = __expf(a1.z); a1.w = __expf(a1.w);
            b1.x = __expf(b1.x); b1.y = __expf(b1.y);
            b1.z = __expf(b1.z); b1.w = __expf(b1.w);
            float s0 = (a0.x + a0.y) + (a0.z + a0.w) + (b0.x + b0.y) + (b0.z + b0.w);
            float s1 = (a1.x + a1.y) + (a1.z + a1.w) + (b1.x + b1.y) + (b1.z + b1.w);
#pragma unroll
            for (int o = 16; o; o >>= 1) {
                s0 += __shfl_xor_sync(0xffffffffu, s0, o);
                s1 += __shfl_xor_sync(0xffffffffu, s1, o);
            }
            float* slot = red + ((rr >> 1) & 1) * 16;
            if (lane == 0) {
                slot[wid * 2] = s0;
                slot[wid * 2 + 1] = s1;
            }
            __syncthreads();
            float t0 = 0.f, t1 = 0.f;
#pragma unroll
            for (int w = 0; w < 8; w++) {
                t0 += slot[w * 2];
                t1 += slot[w * 2 + 1];
            }
            const float i0 = 1.0f / t0, i1 = 1.0f / t1;
            a0.x *= i0; a0.y *= i0; a0.z *= i0; a0.w *= i0;
            b0.x *= i0; b0.y *= i0; b0.z *= i0; b0.w *= i0;
            a1.x *= i1; a1.y *= i1; a1.z *= i1; a1.w *= i1;
            b1.x *= i1; b1.y *= i1; b1.z *= i1; b1.w *= i1;
            __stcs((float4*)(p0 + tid * 4), a0);
            __stcs((float4*)(p0 + 1024 + tid * 4), b0);
            __stcs((float4*)(p1 + tid * 4), a1);
            __stcs((float4*)(p1 + 1024 + tid * 4), b1);
        }
        return;
    }

    const int mt = bid >> 3, nt = bid & 7;
    const int lane = tid & 31, wid = tid >> 5;
    const int g = lane >> 2, t4 = lane & 3;
    const int wm = (wid & 1) * 64, wn = (wid >> 1) * 32;
    const uint32_t* At = g_op + (size_t)(mt * 32) * 4096;
    const uint32_t* Bt = g_wp + (size_t)(3 * 256 + nt * 32) * 4096;

#pragma unroll
    for (int i = 0; i < 4; i++) {
        cpa16(sm + tid * 4 + i * 1024, At + tid * 4 + i * 1024);
        cpa16(sm + 4096 + tid * 4 + i * 1024, Bt + tid * 4 + i * 1024);
    }
    CPA_COMMIT;

    float acc[4][4][4] = {};

    for (int kt = 0; kt < 32; kt++) {
        uint32_t* S = sm + (kt & 1) * 8192;
        CPA_WAIT(0);
        __syncthreads();
        if (kt + 1 < 32) {
            uint32_t* Nx = sm + ((kt + 1) & 1) * 8192;
            const uint32_t* An = At + (kt + 1) * 4096;
            const uint32_t* Bn = Bt + (kt + 1) * 4096;
#pragma unroll
            for (int i = 0; i < 4; i++) {
                cpa16(Nx + tid * 4 + i * 1024, An + tid * 4 + i * 1024);
                cpa16(Nx + 4096 + tid * 4 + i * 1024, Bn + tid * 4 + i * 1024);
            }
            CPA_COMMIT;
        }
#pragma unroll
        for (int s = 0; s < 4; s++) {
            uint4 av[4], bv[2];
#pragma unroll
            for (int mi = 0; mi < 4; mi++)
                av[mi] = *(const uint4*)&S[frag_addr(4, (wm >> 4) + mi, s, g, t4)];
#pragma unroll
            for (int bi = 0; bi < 2; bi++)
                bv[bi] = *(const uint4*)&S[4096 + frag_addr(4, (wn >> 4) + bi, s, g, t4)];
#pragma unroll
            for (int mi = 0; mi < 4; mi++)
#pragma unroll
                for (int bi = 0; bi < 2; bi++) {
                    mma8(acc[mi][bi * 2], av[mi].x, av[mi].y, av[mi].z, av[mi].w,
                         bv[bi].x, bv[bi].z);
                    mma8(acc[mi][bi * 2 + 1], av[mi].x, av[mi].y, av[mi].z, av[mi].w,
                         bv[bi].y, bv[bi].w);
                }
        }
    }

#pragma unroll
    for (int mi = 0; mi < 4; mi++)
#pragma unroll
        for (int ni = 0; ni < 4; ni++)
#pragma unroll
            for (int e = 0; e < 4; e++) {
                int row = mt * 128 + wm + mi * 16 + g + (e >> 1) * 8;
                int col = nt * 128 + wn + ni * 8 + t4 * 2 + (e & 1);
                C[(size_t)row * DM + col] = acc[mi][ni][e];
            }
}

extern "C" void kernel_launch(void* const* d_in, const int* in_sizes, int n_in,
                              void* d_out, int out_size) {
    const float* q_in = (const float*)d_in[0];
    const float* k_in = (const float*)d_in[1];
    const float* v_in = (const float*)d_in[2];
    const int* mask = (const int*)d_in[3];
    const float* Wq = (const float*)d_in[4];
    const float* Wk = (const float*)d_in[5];
    const float* Wv = (const float*)d_in[6];
    const float* Wo = (const float*)d_in[7];

    float* out = (float*)d_out;           // [S, DM]
    float* attn = out + (size_t)SQ * DM;  // [H, S, S]

    static int smem_set = 0;
    if (!smem_set) {
        cudaFuncSetAttribute(fused_attn, cudaFuncAttributeMaxDynamicSharedMemorySize,
                             114688);
        cudaFuncSetAttribute(gemm_qkv, cudaFuncAttributeMaxDynamicSharedMemorySize,
                             65536);
        cudaFuncSetAttribute(out_softmax, cudaFuncAttributeMaxDynamicSharedMemorySize,
                             65536);
        smem_set = 1;
    }

    prep<<<2816, 256>>>(q_in, k_in, v_in, Wq, Wk, Wv, Wo, mask);

    dim3 gQKV(8, 16, 3);
    gemm_qkv<<<gQKV, 256, 65536>>>();

    dim3 gFused(SQ / 128, NH, 1);  // (16, 16)
    fused_attn<<<gFused, 256, 114688>>>(attn);

    out_softmax<<<128 + 2048, 256, 65536>>>(out, attn);
}

// round 9
// speedup vs baseline: 1.5561x; 1.5561x over previous
#include <cuda_runtime.h>
#include <cstdint>

#define SQ 2048
#define DM 1024
#define NH 16
#define HD 64
#define NT (SQ / 64)  // 32 column tiles in fused

// Scratch (allocation-free)
__device__ float g_rsum[NH * SQ];            // per-row softmax denominators
__device__ uint32_t g_mbits[64 * SQ];        // mask bitmask, [wordcol][row]
__device__ uint32_t g_ap[3 * 512 * 4096];    // q,k,v inputs: permuted [z][mt][kt] tiles
__device__ uint32_t g_wp[4 * 256 * 4096];    // Wq,Wk,Wv,Wo: permuted [w][nt][kt] tiles
__device__ uint32_t g_op[512 * 4096];        // attention out O: permuted [mt][kt] tiles
__device__ uint32_t g_qp[NH * 16 * 8192];    // Q proj (pre-scaled 1/8), per (h, mtile)
__device__ uint32_t g_kp[NH * 32 * 4096];    // K proj, permuted per (h, ttile)
__device__ uint32_t g_vp[NH * 32 * 4096];    // V^T proj, permuted per (h, ttile)

__device__ __forceinline__ uint32_t f2tf(float f) {
    uint32_t u;
    asm("cvt.rna.tf32.f32 %0, %1;" : "=r"(u) : "f"(f));
    return u;
}

__device__ __forceinline__ void mma8(float* c, uint32_t a0, uint32_t a1, uint32_t a2,
                                     uint32_t a3, uint32_t b0, uint32_t b1) {
    asm("mma.sync.aligned.m16n8k8.row.col.f32.tf32.tf32.f32 "
        "{%0,%1,%2,%3},{%4,%5,%6,%7},{%8,%9},{%0,%1,%2,%3};"
        : "+f"(c[0]), "+f"(c[1]), "+f"(c[2]), "+f"(c[3])
        : "r"(a0), "r"(a1), "r"(a2), "r"(a3), "r"(b0), "r"(b1));
}

// Permuted fragment-major layout (one LDS.128 per mma fragment).
__device__ __forceinline__ int perm_word(int NS, int r, int k) {
    int gg = r & 7;
    int kk = k & 7;
    int L = gg * 4 + ((kk & 3) ^ (gg & 3));
    return (((r >> 4) * NS + (k >> 3)) * 32 + L) * 4 + ((r >> 3) & 1) + 2 * (kk >> 2);
}
__device__ __forceinline__ void sts_perm4(uint32_t* S, int NS, int r, int c4, uint4 u) {
    int gg = r & 7;
    int base = (((r >> 4) * NS + (c4 >> 3)) * 32 + gg * 4) * 4 + ((r >> 3) & 1) +
               2 * ((c4 >> 2) & 1);
    int x = gg & 3;
    S[base + (0 ^ x) * 4] = u.x;
    S[base + (1 ^ x) * 4] = u.y;
    S[base + (2 ^ x) * 4] = u.z;
    S[base + (3 ^ x) * 4] = u.w;
}
__device__ __forceinline__ int frag_addr(int NS, int band, int s, int g, int t4) {
    return ((band * NS + s) * 32 + g * 4 + (t4 ^ (g & 3))) * 4;
}

__device__ __forceinline__ void cpa16(void* dst, const void* src) {
    uint32_t s = (uint32_t)__cvta_generic_to_shared(dst);
    asm volatile("cp.async.cg.shared.global [%0], [%1], 16;" ::"r"(s), "l"(src));
}
#define CPA_COMMIT asm volatile("cp.async.commit_group;")
#define CPA_WAIT(n) asm volatile("cp.async.wait_group %0;" ::"n"(n))

// ---------------------------------------------------------------------------
// Pre-pass: tf32-round + pre-permute activations (blocks 0..1535) and weights
// (1536..2559); mask bit-compaction (2560+).
// ---------------------------------------------------------------------------
__global__ __launch_bounds__(256) void prep(
    const float* __restrict__ q_in, const float* __restrict__ k_in,
    const float* __restrict__ v_in, const float* __restrict__ Wq,
    const float* __restrict__ Wk, const float* __restrict__ Wv,
    const float* __restrict__ Wo, const int* __restrict__ mask) {
    const int bid = blockIdx.x;
    const int tid = threadIdx.x;

    if (bid >= 2560) {  // mask compaction: 256 blocks x 8 rows (warp per row)
        const int lane = tid & 31, wid = tid >> 5;
        const int row = (bid - 2560) * 8 + wid;
        const int4* mp = (const int4*)(mask + (size_t)row * SQ + lane * 64);
        uint32_t w0 = 0, w1 = 0;
#pragma unroll
        for (int i = 0; i < 16; i++) {
            int4 m = mp[i];
            uint32_t bits = (m.x != 0 ? 1u : 0u) | (m.y != 0 ? 2u : 0u) |
                            (m.z != 0 ? 4u : 0u) | (m.w != 0 ? 8u : 0u);
            if (i < 8)
                w0 |= bits << (i * 4);
            else
                w1 |= bits << ((i - 8) * 4);
        }
        g_mbits[(lane * 2 + 0) * SQ + row] = w0;
        g_mbits[(lane * 2 + 1) * SQ + row] = w1;
        return;
    }

    __shared__ uint32_t sp[4096];
    const float* src;
    uint32_t* dst;
    int r0, c0;
    if (bid < 1536) {  // activation tile: z, mt(16), kt(32)
        int z = bid >> 9, rem = bid & 511;
        src = z == 0 ? q_in : z == 1 ? k_in : v_in;
        r0 = (rem >> 5) * 128;
        c0 = (rem & 31) * 32;
        dst = g_ap + bid * 4096;
    } else {  // weight tile: w(4), nt(8), kt(32)
        int wb = bid - 1536;
        int w = wb >> 8, rem = wb & 255;
        src = w == 0 ? Wq : w == 1 ? Wk : w == 2 ? Wv : Wo;
        r0 = (rem >> 5) * 128;
        c0 = (rem & 31) * 32;
        dst = g_wp + wb * 4096;
    }
#pragma unroll
    for (int i = 0; i < 4; i++) {
        int idx = tid + i * 256, r = idx >> 3, c4 = (idx & 7) * 4;
        float4 v = *(const float4*)(src + (size_t)(r0 + r) * DM + c0 + c4);
        uint4 u = {f2tf(v.x), f2tf(v.y), f2tf(v.z), f2tf(v.w)};
        sts_perm4(sp, 4, r, c4, u);
    }
    __syncthreads();
#pragma unroll
    for (int i = 0; i < 4; i++)
        *(uint4*)(dst + tid * 4 + i * 1024) = *(const uint4*)(sp + tid * 4 + i * 1024);
}

// ---------------------------------------------------------------------------
// QKV projection GEMMs from pre-permuted tiles. cp.async double-buffered.
// Q epilogue pre-scales by 1/8 (exponent shift on tf32 -> bit-exact).
// ---------------------------------------------------------------------------
__global__ __launch_bounds__(256, 2) void gemm_qkv() {
    extern __shared__ uint32_t sm[];  // 2 stages x (A 4096 | B 4096)
    const int z = blockIdx.z, mt = blockIdx.y, nt = blockIdx.x;
    const int tid = threadIdx.x, lane = tid & 31, wid = tid >> 5;
    const int g = lane >> 2, t4 = lane & 3;
    const int wm = (wid & 1) * 64, wn = (wid >> 1) * 32;
    const uint32_t* At = g_ap + (size_t)(z * 512 + mt * 32) * 4096;
    const uint32_t* Bt = g_wp + (size_t)(z * 256 + nt * 32) * 4096;

#pragma unroll
    for (int i = 0; i < 4; i++) {
        cpa16(sm + tid * 4 + i * 1024, At + tid * 4 + i * 1024);
        cpa16(sm + 4096 + tid * 4 + i * 1024, Bt + tid * 4 + i * 1024);
    }
    CPA_COMMIT;

    float acc[4][4][4] = {};

    for (int kt = 0; kt < 32; kt++) {
        uint32_t* S = sm + (kt & 1) * 8192;
        CPA_WAIT(0);
        __syncthreads();
        if (kt + 1 < 32) {
            uint32_t* Nx = sm + ((kt + 1) & 1) * 8192;
            const uint32_t* An = At + (kt + 1) * 4096;
            const uint32_t* Bn = Bt + (kt + 1) * 4096;
#pragma unroll
            for (int i = 0; i < 4; i++) {
                cpa16(Nx + tid * 4 + i * 1024, An + tid * 4 + i * 1024);
                cpa16(Nx + 4096 + tid * 4 + i * 1024, Bn + tid * 4 + i * 1024);
            }
            CPA_COMMIT;
        }
#pragma unroll
        for (int s = 0; s < 4; s++) {
            uint4 av[4], bv[2];
#pragma unroll
            for (int mi = 0; mi < 4; mi++)
                av[mi] = *(const uint4*)&S[frag_addr(4, (wm >> 4) + mi, s, g, t4)];
#pragma unroll
            for (int bi = 0; bi < 2; bi++)
                bv[bi] = *(const uint4*)&S[4096 + frag_addr(4, (wn >> 4) + bi, s, g, t4)];
#pragma unroll
            for (int mi = 0; mi < 4; mi++)
#pragma unroll
                for (int bi = 0; bi < 2; bi++) {
                    mma8(acc[mi][bi * 2], av[mi].x, av[mi].y, av[mi].z, av[mi].w,
                         bv[bi].x, bv[bi].z);
                    mma8(acc[mi][bi * 2 + 1], av[mi].x, av[mi].y, av[mi].z, av[mi].w,
                         bv[bi].y, bv[bi].w);
                }
        }
    }

    // epilogue: tf32-round, write per-head permuted layouts (Q scaled by 1/8)
#pragma unroll
    for (int mi = 0; mi < 4; mi++)
#pragma unroll
        for (int ni = 0; ni < 4; ni++)
#pragma unroll
            for (int e = 0; e < 4; e++) {
                int row = wm + mi * 16 + g + ((e >> 1) * 8);  // 0..127
                int col = wn + ni * 8 + t4 * 2 + (e & 1);     // 0..127
                int gn = nt * 128 + col;
                int h = gn >> 6, c64 = gn & 63;
                if (z == 0) {
                    g_qp[(h * 16 + mt) * 8192 + perm_word(8, row, c64)] =
                        f2tf(acc[mi][ni][e] * 0.125f);
                } else {
                    uint32_t val = f2tf(acc[mi][ni][e]);
                    int tile = mt * 2 + (row >> 6);
                    int r64 = row & 63;
                    if (z == 1)
                        g_kp[(h * 32 + tile) * 4096 + perm_word(8, r64, c64)] = val;
                    else
                        g_vp[(h * 32 + tile) * 4096 + perm_word(8, c64, r64)] = val;
                }
            }
}

// ---------------------------------------------------------------------------
// Fused attention + exp + row-sum (round-7 structure). S = (Q/8)K^T, masked;
// attn <- exp(v) streaming; Sp <- tf32(v); O += S@V; rsum -> g_rsum.
// ---------------------------------------------------------------------------
__global__ __launch_bounds__(256, 2) void fused_attn(float* __restrict__ attn) {
    extern __shared__ uint32_t sm[];
    uint32_t* Qp = sm;            // 8192 w
    uint32_t* Kp = sm + 8192;     // 2 x 4096 w
    uint32_t* Vp = sm + 16384;    // 4096 w (reused as rs[4][128] after loop)
    uint32_t* Sp = sm + 20480;    // 8192 w

    const int tid = threadIdx.x, lane = tid & 31, wid = tid >> 5;
    const int g = lane >> 2, t4 = lane & 3;
    const int wm = (wid & 1) * 64, wn = (wid >> 1) * 16;
    const int h = blockIdx.y, mt = blockIdx.x;
    const int m0 = mt * 128;
    const int slot = wn >> 5;
    const size_t attn_base = (size_t)h * SQ * SQ;
    const uint32_t* kg = g_kp + h * 32 * 4096;
    const uint32_t* vg = g_vp + h * 32 * 4096;

    // prologue: cp.async K[0] and Q
#pragma unroll
    for (int i = 0; i < 4; i++)
        cpa16(Kp + tid * 4 + i * 1024, kg + tid * 4 + i * 1024);
    {
        const uint32_t* qg = g_qp + (h * 16 + mt) * 8192;
#pragma unroll
        for (int i = 0; i < 8; i++)
            cpa16(Qp + tid * 4 + i * 1024, qg + tid * 4 + i * 1024);
    }
    CPA_COMMIT;

    float oacc[4][2][4] = {};
    float rsum[4][2] = {};

    for (int tt = 0; tt < NT; tt++) {
        const int t0 = tt * 64;
        uint32_t* Kc = Kp + (tt & 1) * 4096;

        CPA_WAIT(0);
        __syncthreads();

        uint32_t mw[4][2];
        {
            const uint32_t* mb = g_mbits + (tt * 2 + slot) * SQ + m0;
#pragma unroll
            for (int mi = 0; mi < 4; mi++)
#pragma unroll
                for (int e2 = 0; e2 < 2; e2++)
                    mw[mi][e2] = mb[wm + mi * 16 + g + e2 * 8];
        }

#pragma unroll
        for (int i = 0; i < 4; i++)
            cpa16(Vp + tid * 4 + i * 1024, vg + tt * 4096 + tid * 4 + i * 1024);
        CPA_COMMIT;
        if (tt + 1 < NT) {
            uint32_t* Kn = Kp + ((tt + 1) & 1) * 4096;
#pragma unroll
            for (int i = 0; i < 4; i++)
                cpa16(Kn + tid * 4 + i * 1024, kg + (tt + 1) * 4096 + tid * 4 + i * 1024);
        }
        CPA_COMMIT;

        // S = (Q/8) K^T  (scale folded into Q)
        float sacc[4][2][4] = {};
#pragma unroll
        for (int s = 0; s < 8; s++) {
            uint4 aq[4];
#pragma unroll
            for (int mi = 0; mi < 4; mi++)
                aq[mi] = *(const uint4*)&Qp[frag_addr(8, (wm >> 4) + mi, s, g, t4)];
            uint4 bk = *(const uint4*)&Kc[frag_addr(8, wn >> 4, s, g, t4)];
#pragma unroll
            for (int mi = 0; mi < 4; mi++) {
                mma8(sacc[mi][0], aq[mi].x, aq[mi].y, aq[mi].z, aq[mi].w, bk.x, bk.z);
                mma8(sacc[mi][1], aq[mi].x, aq[mi].y, aq[mi].z, aq[mi].w, bk.y, bk.w);
            }
        }

        // epilogue: mask; attn <- exp(v) streaming; Sp <- tf32(v); rsum += exp
#pragma unroll
        for (int mi = 0; mi < 4; mi++)
#pragma unroll
            for (int ni = 0; ni < 2; ni++)
#pragma unroll
                for (int e2 = 0; e2 < 2; e2++) {
                    int rl = wm + mi * 16 + g + e2 * 8;
                    int cl = wn + ni * 8 + t4 * 2;
                    int rg = m0 + rl, cg = t0 + cl;
                    float v0 = sacc[mi][ni][e2 * 2];
                    float v1 = sacc[mi][ni][e2 * 2 + 1];
                    uint32_t w = mw[mi][e2];
                    if ((w >> (cl & 31)) & 1) v0 = -1e-7f;
                    if ((w >> ((cl & 31) + 1)) & 1) v1 = -1e-7f;
                    float e0 = __expf(v0), e1 = __expf(v1);
                    __stcs((float2*)(attn + attn_base + (size_t)rg * SQ + cg),
                           make_float2(e0, e1));
                    rsum[mi][e2] += e0 + e1;
                    Sp[perm_word(8, rl, cl)] = f2tf(v0);
                    Sp[perm_word(8, rl, cl + 1)] = f2tf(v1);
                }

        CPA_WAIT(1);
        __syncthreads();

        // O += S @ V
#pragma unroll
        for (int s = 0; s < 8; s++) {
            uint4 as[4];
#pragma unroll
            for (int mi = 0; mi < 4; mi++)
                as[mi] = *(const uint4*)&Sp[frag_addr(8, (wm >> 4) + mi, s, g, t4)];
            uint4 bv = *(const uint4*)&Vp[frag_addr(8, wn >> 4, s, g, t4)];
#pragma unroll
            for (int mi = 0; mi < 4; mi++) {
                mma8(oacc[mi][0], as[mi].x, as[mi].y, as[mi].z, as[mi].w, bv.x, bv.z);
                mma8(oacc[mi][1], as[mi].x, as[mi].y, as[mi].z, as[mi].w, bv.y, bv.w);
            }
        }
    }

    // O epilogue: tf32-round + permuted tile write for output GEMM
#pragma unroll
    for (int mi = 0; mi < 4; mi++)
#pragma unroll
        for (int ni = 0; ni < 2; ni++)
#pragma unroll
            for (int e = 0; e < 4; e++) {
                int rl = wm + mi * 16 + g + (e >> 1) * 8;
                int col = wn + ni * 8 + t4 * 2 + (e & 1);  // 0..63
                int kt = h * 2 + (col >> 5);
                g_op[(mt * 32 + kt) * 4096 + perm_word(4, rl, col & 31)] =
                    f2tf(oacc[mi][ni][e]);
            }

    // deterministic row-sum reduction
    __syncthreads();
    float* rs = (float*)Vp;
    rs[tid] = 0.f;
    rs[tid + 256] = 0.f;
    __syncthreads();
#pragma unroll
    for (int mi = 0; mi < 4; mi++)
#pragma unroll
        for (int e2 = 0; e2 < 2; e2++) {
            float r = rsum[mi][e2];
            r += __shfl_xor_sync(0xffffffffu, r, 1);
            r += __shfl_xor_sync(0xffffffffu, r, 2);
            if (t4 == 0) rs[(wid >> 1) * 128 + wm + mi * 16 + g + e2 * 8] = r;
        }
    __syncthreads();
    if (tid < 128)
        g_rsum[h * SQ + m0 + tid] =
            rs[tid] + rs[128 + tid] + rs[256 + tid] + rs[384 + tid];
}

// ---------------------------------------------------------------------------
// Heterogeneous tail: blocks 0..127 = output projection (cp.async GEMM);
// blocks 128+ = attn scale stream, 4 rows in flight, no barriers.
// ---------------------------------------------------------------------------
__global__ __launch_bounds__(256, 2) void out_scale(float* __restrict__ C,
                                                    float* __restrict__ attn) {
    extern __shared__ uint32_t sm[];
    const int bid = blockIdx.x;
    const int tid = threadIdx.x;

    if (bid >= 128) {  // scale: 2048 blocks x 16 rows, 4 rows per iteration
        const int r0 = (bid - 128) * 16;
        for (int rr = 0; rr < 16; rr += 4) {
            float4 va[4], vb[4];
            float inv[4];
#pragma unroll
            for (int r = 0; r < 4; r++) {
                const int row = r0 + rr + r;
                inv[r] = 1.0f / g_rsum[row];
                const float* p = attn + (size_t)row * SQ;
                va[r] = __ldcs((const float4*)(p + tid * 4));
                vb[r] = __ldcs((const float4*)(p + 1024 + tid * 4));
            }
#pragma unroll
            for (int r = 0; r < 4; r++) {
                float* p = attn + (size_t)(r0 + rr + r) * SQ;
                va[r].x *= inv[r]; va[r].y *= inv[r];
                va[r].z *= inv[r]; va[r].w *= inv[r];
                vb[r].x *= inv[r]; vb[r].y *= inv[r];
                vb[r].z *= inv[r]; vb[r].w *= inv[r];
                __stcs((float4*)(p + tid * 4), va[r]);
                __stcs((float4*)(p + 1024 + tid * 4), vb[r]);
            }
        }
        return;
    }

    const int mt = bid >> 3, nt = bid & 7;
    const int lane = tid & 31, wid = tid >> 5;
    const int g = lane >> 2, t4 = lane & 3;
    const int wm = (wid & 1) * 64, wn = (wid >> 1) * 32;
    const uint32_t* At = g_op + (size_t)(mt * 32) * 4096;
    const uint32_t* Bt = g_wp + (size_t)(3 * 256 + nt * 32) * 4096;

#pragma unroll
    for (int i = 0; i < 4; i++) {
        cpa16(sm + tid * 4 + i * 1024, At + tid * 4 + i * 1024);
        cpa16(sm + 4096 + tid * 4 + i * 1024, Bt + tid * 4 + i * 1024);
    }
    CPA_COMMIT;

    float acc[4][4][4] = {};

    for (int kt = 0; kt < 32; kt++) {
        uint32_t* S = sm + (kt & 1) * 8192;
        CPA_WAIT(0);
        __syncthreads();
        if (kt + 1 < 32) {
            uint32_t* Nx = sm + ((kt + 1) & 1) * 8192;
            const uint32_t* An = At + (kt + 1) * 4096;
            const uint32_t* Bn = Bt + (kt + 1) * 4096;
#pragma unroll
            for (int i = 0; i < 4; i++) {
                cpa16(Nx + tid * 4 + i * 1024, An + tid * 4 + i * 1024);
                cpa16(Nx + 4096 + tid * 4 + i * 1024, Bn + tid * 4 + i * 1024);
            }
            CPA_COMMIT;
        }
#pragma unroll
        for (int s = 0; s < 4; s++) {
            uint4 av[4], bv[2];
#pragma unroll
            for (int mi = 0; mi < 4; mi++)
                av[mi] = *(const uint4*)&S[frag_addr(4, (wm >> 4) + mi, s, g, t4)];
#pragma unroll
            for (int bi = 0; bi < 2; bi++)
                bv[bi] = *(const uint4*)&S[4096 + frag_addr(4, (wn >> 4) + bi, s, g, t4)];
#pragma unroll
            for (int mi = 0; mi < 4; mi++)
#pragma unroll
                for (int bi = 0; bi < 2; bi++) {
                    mma8(acc[mi][bi * 2], av[mi].x, av[mi].y, av[mi].z, av[mi].w,
                         bv[bi].x, bv[bi].z);
                    mma8(acc[mi][bi * 2 + 1], av[mi].x, av[mi].y, av[mi].z, av[mi].w,
                         bv[bi].y, bv[bi].w);
                }
        }
    }

#pragma unroll
    for (int mi = 0; mi < 4; mi++)
#pragma unroll
        for (int ni = 0; ni < 4; ni++)
#pragma unroll
            for (int e = 0; e < 4; e++) {
                int row = mt * 128 + wm + mi * 16 + g + (e >> 1) * 8;
                int col = nt * 128 + wn + ni * 8 + t4 * 2 + (e & 1);
                C[(size_t)row * DM + col] = acc[mi][ni][e];
            }
}

extern "C" void kernel_launch(void* const* d_in, const int* in_sizes, int n_in,
                              void* d_out, int out_size) {
    const float* q_in = (const float*)d_in[0];
    const float* k_in = (const float*)d_in[1];
    const float* v_in = (const float*)d_in[2];
    const int* mask = (const int*)d_in[3];
    const float* Wq = (const float*)d_in[4];
    const float* Wk = (const float*)d_in[5];
    const float* Wv = (const float*)d_in[6];
    const float* Wo = (const float*)d_in[7];

    float* out = (float*)d_out;           // [S, DM]
    float* attn = out + (size_t)SQ * DM;  // [H, S, S]

    static int smem_set = 0;
    if (!smem_set) {
        cudaFuncSetAttribute(fused_attn, cudaFuncAttributeMaxDynamicSharedMemorySize,
                             114688);
        cudaFuncSetAttribute(gemm_qkv, cudaFuncAttributeMaxDynamicSharedMemorySize,
                             65536);
        cudaFuncSetAttribute(out_scale, cudaFuncAttributeMaxDynamicSharedMemorySize,
                             65536);
        smem_set = 1;
    }

    prep<<<2816, 256>>>(q_in, k_in, v_in, Wq, Wk, Wv, Wo, mask);

    dim3 gQKV(8, 16, 3);
    gemm_qkv<<<gQKV, 256, 65536>>>();

    dim3 gFused(SQ / 128, NH, 1);  // (16, 16)
    fused_attn<<<gFused, 256, 114688>>>(attn);

    out_scale<<<128 + 2048, 256, 65536>>>(out, attn);
}

// round 10
// speedup vs baseline: 2.2441x; 1.4421x over previous
#include <cuda_runtime.h>
#include <cuda_fp16.h>
#include <cstdint>

#define SQ 2048
#define DM 1024
#define NH 16
#define HD 64
#define NT (SQ / 64)  // 32 column tiles in fused

// All operand tensors stored as fp16x2 words (low half = even index).
// Tiles: 128 rows x 32 words (NS=4) for A/B GEMM tiles; 64 x 32 w for K/V^T.
__device__ float g_rsum[NH * SQ];            // per-row softmax denominators
__device__ uint32_t g_mbits[64 * SQ];        // mask bitmask, [wordcol][row]
__device__ uint32_t g_ap[3 * 256 * 4096];    // q,k,v inputs: permuted [z][mt][kt]
__device__ uint32_t g_wp[4 * 128 * 4096];    // Wq,Wk,Wv,Wo: permuted [w][nt][kt]
__device__ uint32_t g_op[256 * 4096];        // attention out O: permuted [mt][kt]
__device__ uint32_t g_qp[NH * 16 * 4096];    // Q proj (pre-scaled 1/8), per (h, mt)
__device__ uint32_t g_kp[NH * 32 * 2048];    // K proj, per (h, ttile)
__device__ uint32_t g_vp[NH * 32 * 2048];    // V^T proj, per (h, ttile)

__device__ __forceinline__ uint32_t pk(float a, float b) {
    __half2 h = __floats2half2_rn(a, b);
    return *reinterpret_cast<uint32_t*>(&h);
}

// m16n8k16 fp16 MMA, fp32 accumulate.
__device__ __forceinline__ void mma16(float* c, uint32_t a0, uint32_t a1, uint32_t a2,
                                      uint32_t a3, uint32_t b0, uint32_t b1) {
    asm("mma.sync.aligned.m16n8k16.row.col.f32.f16.f16.f32 "
        "{%0,%1,%2,%3},{%4,%5,%6,%7},{%8,%9},{%0,%1,%2,%3};"
        : "+f"(c[0]), "+f"(c[1]), "+f"(c[2]), "+f"(c[3])
        : "r"(a0), "r"(a1), "r"(a2), "r"(a3), "r"(b0), "r"(b1));
}

// Permuted fragment-major layout over 32-bit words (word = fp16 pair).
__device__ __forceinline__ int perm_word(int NS, int r, int k) {
    int gg = r & 7;
    int kk = k & 7;
    int L = gg * 4 + ((kk & 3) ^ (gg & 3));
    return (((r >> 4) * NS + (k >> 3)) * 32 + L) * 4 + ((r >> 3) & 1) + 2 * (kk >> 2);
}
__device__ __forceinline__ void sts_perm4(uint32_t* S, int NS, int r, int c4, uint4 u) {
    int gg = r & 7;
    int base = (((r >> 4) * NS + (c4 >> 3)) * 32 + gg * 4) * 4 + ((r >> 3) & 1) +
               2 * ((c4 >> 2) & 1);
    int x = gg & 3;
    S[base + (0 ^ x) * 4] = u.x;
    S[base + (1 ^ x) * 4] = u.y;
    S[base + (2 ^ x) * 4] = u.z;
    S[base + (3 ^ x) * 4] = u.w;
}
__device__ __forceinline__ int frag_addr(int NS, int band, int s, int g, int t4) {
    return ((band * NS + s) * 32 + g * 4 + (t4 ^ (g & 3))) * 4;
}

__device__ __forceinline__ void cpa16(void* dst, const void* src) {
    uint32_t s = (uint32_t)__cvta_generic_to_shared(dst);
    asm volatile("cp.async.cg.shared.global [%0], [%1], 16;" ::"r"(s), "l"(src));
}
#define CPA_COMMIT asm volatile("cp.async.commit_group;")
#define CPA_WAIT(n) asm volatile("cp.async.wait_group %0;" ::"n"(n))

// ---------------------------------------------------------------------------
// Pre-pass: fp16-convert + pre-permute activations (blocks 0..767) and weights
// (768..1279); mask bit-compaction (1280+). Tile = 128 rows x 64 k = 32 words.
// ---------------------------------------------------------------------------
__global__ __launch_bounds__(256) void prep(
    const float* __restrict__ q_in, const float* __restrict__ k_in,
    const float* __restrict__ v_in, const float* __restrict__ Wq,
    const float* __restrict__ Wk, const float* __restrict__ Wv,
    const float* __restrict__ Wo, const int* __restrict__ mask) {
    const int bid = blockIdx.x;
    const int tid = threadIdx.x;

    if (bid >= 1280) {  // mask compaction: 256 blocks x 8 rows (warp per row)
        const int lane = tid & 31, wid = tid >> 5;
        const int row = (bid - 1280) * 8 + wid;
        const int4* mp = (const int4*)(mask + (size_t)row * SQ + lane * 64);
        uint32_t w0 = 0, w1 = 0;
#pragma unroll
        for (int i = 0; i < 16; i++) {
            int4 m = mp[i];
            uint32_t bits = (m.x != 0 ? 1u : 0u) | (m.y != 0 ? 2u : 0u) |
                            (m.z != 0 ? 4u : 0u) | (m.w != 0 ? 8u : 0u);
            if (i < 8)
                w0 |= bits << (i * 4);
            else
                w1 |= bits << ((i - 8) * 4);
        }
        g_mbits[(lane * 2 + 0) * SQ + row] = w0;
        g_mbits[(lane * 2 + 1) * SQ + row] = w1;
        return;
    }

    __shared__ uint32_t sp[4096];
    const float* src;
    uint32_t* dst;
    int r0, c0;
    if (bid < 768) {  // activation tile: z(3), mt(16), kt(16)
        int z = bid >> 8, rem = bid & 255;
        src = z == 0 ? q_in : z == 1 ? k_in : v_in;
        r0 = (rem >> 4) * 128;
        c0 = (rem & 15) * 64;
        dst = g_ap + (size_t)bid * 4096;
    } else {  // weight tile: w(4), nt(8), kt(16)
        int wb = bid - 768;
        int w = wb >> 7, rem = wb & 127;
        src = w == 0 ? Wq : w == 1 ? Wk : w == 2 ? Wv : Wo;
        r0 = (rem >> 4) * 128;
        c0 = (rem & 15) * 64;
        dst = g_wp + (size_t)wb * 4096;
    }
#pragma unroll
    for (int i = 0; i < 4; i++) {
        int idx = tid + i * 256, r = idx >> 3, c4 = (idx & 7) * 4;  // word col
        const float* p = src + (size_t)(r0 + r) * DM + c0 + 2 * c4;
        float4 f0 = *(const float4*)p;
        float4 f1 = *(const float4*)(p + 4);
        uint4 u = {pk(f0.x, f0.y), pk(f0.z, f0.w), pk(f1.x, f1.y), pk(f1.z, f1.w)};
        sts_perm4(sp, 4, r, c4, u);
    }
    __syncthreads();
#pragma unroll
    for (int i = 0; i < 4; i++)
        *(uint4*)(dst + tid * 4 + i * 1024) = *(const uint4*)(sp + tid * 4 + i * 1024);
}

// ---------------------------------------------------------------------------
// QKV projection GEMMs (fp16 operands). BM=128, BN=128, BK=64 (32 words),
// 16 stages, cp.async double-buffered. Q pre-scaled by 1/8. V epilogue does a
// smem-bounce transpose to produce V^T (t-pairs packed per word).
// ---------------------------------------------------------------------------
__global__ __launch_bounds__(256, 2) void gemm_qkv() {
    extern __shared__ uint32_t sm[];  // 2 stages x (A 4096 | B 4096)
    const int z = blockIdx.z, mt = blockIdx.y, nt = blockIdx.x;
    const int tid = threadIdx.x, lane = tid & 31, wid = tid >> 5;
    const int g = lane >> 2, t4 = lane & 3;
    const int wm = (wid & 1) * 64, wn = (wid >> 1) * 32;
    const uint32_t* At = g_ap + (size_t)(z * 256 + mt * 16) * 4096;
    const uint32_t* Bt = g_wp + (size_t)(z * 128 + nt * 16) * 4096;

#pragma unroll
    for (int i = 0; i < 4; i++) {
        cpa16(sm + tid * 4 + i * 1024, At + tid * 4 + i * 1024);
        cpa16(sm + 4096 + tid * 4 + i * 1024, Bt + tid * 4 + i * 1024);
    }
    CPA_COMMIT;

    float acc[4][4][4] = {};

    for (int kt = 0; kt < 16; kt++) {
        uint32_t* S = sm + (kt & 1) * 8192;
        CPA_WAIT(0);
        __syncthreads();
        if (kt + 1 < 16) {
            uint32_t* Nx = sm + ((kt + 1) & 1) * 8192;
            const uint32_t* An = At + (kt + 1) * 4096;
            const uint32_t* Bn = Bt + (kt + 1) * 4096;
#pragma unroll
            for (int i = 0; i < 4; i++) {
                cpa16(Nx + tid * 4 + i * 1024, An + tid * 4 + i * 1024);
                cpa16(Nx + 4096 + tid * 4 + i * 1024, Bn + tid * 4 + i * 1024);
            }
            CPA_COMMIT;
        }
#pragma unroll
        for (int s = 0; s < 4; s++) {
            uint4 av[4], bv[2];
#pragma unroll
            for (int mi = 0; mi < 4; mi++)
                av[mi] = *(const uint4*)&S[frag_addr(4, (wm >> 4) + mi, s, g, t4)];
#pragma unroll
            for (int bi = 0; bi < 2; bi++)
                bv[bi] = *(const uint4*)&S[4096 + frag_addr(4, (wn >> 4) + bi, s, g, t4)];
#pragma unroll
            for (int mi = 0; mi < 4; mi++)
#pragma unroll
                for (int bi = 0; bi < 2; bi++) {
                    mma16(acc[mi][bi * 2], av[mi].x, av[mi].y, av[mi].z, av[mi].w,
                          bv[bi].x, bv[bi].z);
                    mma16(acc[mi][bi * 2 + 1], av[mi].x, av[mi].y, av[mi].z, av[mi].w,
                          bv[bi].y, bv[bi].w);
                }
        }
    }

    if (z < 2) {
        // direct packed epilogue (Q scaled by 1/8)
        const float sc = (z == 0) ? 0.125f : 1.0f;
#pragma unroll
        for (int mi = 0; mi < 4; mi++)
#pragma unroll
            for (int ni = 0; ni < 4; ni++) {
                int row = wm + mi * 16 + g;
                int colp = wn + ni * 8 + 2 * t4;
                int gn = nt * 128 + colp;
                int h = gn >> 6, kkw = (gn & 63) >> 1;
                uint32_t w0 = pk(acc[mi][ni][0] * sc, acc[mi][ni][1] * sc);
                uint32_t w1 = pk(acc[mi][ni][2] * sc, acc[mi][ni][3] * sc);
                if (z == 0) {
                    g_qp[(h * 16 + mt) * 4096 + perm_word(4, row, kkw)] = w0;
                    g_qp[(h * 16 + mt) * 4096 + perm_word(4, row + 8, kkw)] = w1;
                } else {
                    int tile = mt * 2 + (row >> 6);
                    int r64 = row & 63;
                    g_kp[(h * 32 + tile) * 2048 + perm_word(4, r64, kkw)] = w0;
                    g_kp[(h * 32 + tile) * 2048 + perm_word(4, r64 + 8, kkw)] = w1;
                }
            }
    } else {
        // V: bounce through smem, transpose, pack t-pairs -> g_vp (V^T)
        __syncthreads();  // mainloop smem reads done
        __half* hb = (__half*)sm;  // [128 rows][130 halves] (pad 2)
#pragma unroll
        for (int mi = 0; mi < 4; mi++)
#pragma unroll
            for (int ni = 0; ni < 4; ni++) {
                int row = wm + mi * 16 + g;
                int colw = ((wn + ni * 8) >> 1) + t4;  // local word col 0..63
                ((uint32_t*)0, 0);
                *(uint32_t*)&hb[row * 130 + 2 * colw] =
                    pk(acc[mi][ni][0], acc[mi][ni][1]);
                *(uint32_t*)&hb[(row + 8) * 130 + 2 * colw] =
                    pk(acc[mi][ni][2], acc[mi][ni][3]);
            }
        __syncthreads();
#pragma unroll
        for (int i = 0; i < 32; i++) {
            int widx = tid + i * 256;       // 0..8191
            int dl = widx >> 6;             // local d 0..127
            int tw = widx & 63;             // t-word 0..63
            __half lo = hb[(2 * tw) * 130 + dl];
            __half hi = hb[(2 * tw + 1) * 130 + dl];
            __half2 hh = __halves2half2(lo, hi);
            int gd = nt * 128 + dl;
            int h = gd >> 6, dr = gd & 63;
            int tt = mt * 2 + (tw >> 5), tkk = tw & 31;
            g_vp[(h * 32 + tt) * 2048 + perm_word(4, dr, tkk)] =
                *(uint32_t*)&hh;
        }
    }
}

// ---------------------------------------------------------------------------
// Fused attention (fp16 MMA) + exp + row-sum. K and V both double-buffered and
// prefetched one tile ahead; sync#2 waits only on the Sp smem handoff.
// smem: Qp 16K | Kp 2x8K | Vp 2x8K | Sp 16K = 64KB.
// ---------------------------------------------------------------------------
__global__ __launch_bounds__(256, 2) void fused_attn(float* __restrict__ attn) {
    extern __shared__ uint32_t sm[];
    uint32_t* Qp = sm;            // 4096 w
    uint32_t* Kp = sm + 4096;     // 2 x 2048 w
    uint32_t* Vp = sm + 8192;     // 2 x 2048 w
    uint32_t* Sp = sm + 12288;    // 4096 w (reused as rs after loop)

    const int tid = threadIdx.x, lane = tid & 31, wid = tid >> 5;
    const int g = lane >> 2, t4 = lane & 3;
    const int wm = (wid & 1) * 64, wn = (wid >> 1) * 16;
    const int h = blockIdx.y, mt = blockIdx.x;
    const int m0 = mt * 128;
    const int slot = wn >> 5;
    const size_t attn_base = (size_t)h * SQ * SQ;
    const uint32_t* kg = g_kp + h * 32 * 2048;
    const uint32_t* vg = g_vp + h * 32 * 2048;

    // prologue: cp.async Q, K[0], V[0] (one group)
    {
        const uint32_t* qg = g_qp + (h * 16 + mt) * 4096;
#pragma unroll
        for (int i = 0; i < 4; i++)
            cpa16(Qp + tid * 4 + i * 1024, qg + tid * 4 + i * 1024);
    }
#pragma unroll
    for (int i = 0; i < 2; i++) {
        cpa16(Kp + tid * 4 + i * 1024, kg + tid * 4 + i * 1024);
        cpa16(Vp + tid * 4 + i * 1024, vg + tid * 4 + i * 1024);
    }
    CPA_COMMIT;

    float oacc[4][2][4] = {};
    float rsum[4][2] = {};

    for (int tt = 0; tt < NT; tt++) {
        const int t0 = tt * 64;
        uint32_t* Kc = Kp + (tt & 1) * 2048;
        uint32_t* Vc = Vp + (tt & 1) * 2048;

        CPA_WAIT(0);      // K[tt], V[tt] (and Q on tt=0) landed
        __syncthreads();  // visible to all; prev AV reads of Sp done

        uint32_t mw[4][2];
        {
            const uint32_t* mb = g_mbits + (tt * 2 + slot) * SQ + m0;
#pragma unroll
            for (int mi = 0; mi < 4; mi++)
#pragma unroll
                for (int e2 = 0; e2 < 2; e2++)
                    mw[mi][e2] = mb[wm + mi * 16 + g + e2 * 8];
        }

        if (tt + 1 < NT) {  // prefetch K,V for next tile
            uint32_t* Kn = Kp + ((tt + 1) & 1) * 2048;
            uint32_t* Vn = Vp + ((tt + 1) & 1) * 2048;
#pragma unroll
            for (int i = 0; i < 2; i++) {
                cpa16(Kn + tid * 4 + i * 1024,
                      kg + (tt + 1) * 2048 + tid * 4 + i * 1024);
                cpa16(Vn + tid * 4 + i * 1024,
                      vg + (tt + 1) * 2048 + tid * 4 + i * 1024);
            }
            CPA_COMMIT;
        }

        // S = (Q/8) K^T   (4 k16-steps over d=64)
        float sacc[4][2][4] = {};
#pragma unroll
        for (int s = 0; s < 4; s++) {
            uint4 aq[4];
#pragma unroll
            for (int mi = 0; mi < 4; mi++)
                aq[mi] = *(const uint4*)&Qp[frag_addr(4, (wm >> 4) + mi, s, g, t4)];
            uint4 bk = *(const uint4*)&Kc[frag_addr(4, wn >> 4, s, g, t4)];
#pragma unroll
            for (int mi = 0; mi < 4; mi++) {
                mma16(sacc[mi][0], aq[mi].x, aq[mi].y, aq[mi].z, aq[mi].w, bk.x, bk.z);
                mma16(sacc[mi][1], aq[mi].x, aq[mi].y, aq[mi].z, aq[mi].w, bk.y, bk.w);
            }
        }

        // epilogue: mask; attn <- exp(v) streaming; Sp <- fp16(v); rsum += exp
#pragma unroll
        for (int mi = 0; mi < 4; mi++)
#pragma unroll
            for (int ni = 0; ni < 2; ni++)
#pragma unroll
                for (int e2 = 0; e2 < 2; e2++) {
                    int rl = wm + mi * 16 + g + e2 * 8;
                    int cl = wn + ni * 8 + t4 * 2;
                    int rg = m0 + rl, cg = t0 + cl;
                    float v0 = sacc[mi][ni][e2 * 2];
                    float v1 = sacc[mi][ni][e2 * 2 + 1];
                    uint32_t w = mw[mi][e2];
                    if ((w >> (cl & 31)) & 1) v0 = -1e-7f;
                    if ((w >> ((cl & 31) + 1)) & 1) v1 = -1e-7f;
                    float e0 = __expf(v0), e1 = __expf(v1);
                    __stcs((float2*)(attn + attn_base + (size_t)rg * SQ + cg),
                           make_float2(e0, e1));
                    rsum[mi][e2] += e0 + e1;
                    Sp[perm_word(4, rl, cl >> 1)] = pk(v0, v1);
                }

        __syncthreads();  // Sp visible (V already resident)

        // O += S @ V
#pragma unroll
        for (int s = 0; s < 4; s++) {
            uint4 as[4];
#pragma unroll
            for (int mi = 0; mi < 4; mi++)
                as[mi] = *(const uint4*)&Sp[frag_addr(4, (wm >> 4) + mi, s, g, t4)];
            uint4 bv = *(const uint4*)&Vc[frag_addr(4, wn >> 4, s, g, t4)];
#pragma unroll
            for (int mi = 0; mi < 4; mi++) {
                mma16(oacc[mi][0], as[mi].x, as[mi].y, as[mi].z, as[mi].w, bv.x, bv.z);
                mma16(oacc[mi][1], as[mi].x, as[mi].y, as[mi].z, as[mi].w, bv.y, bv.w);
            }
        }
    }

    // O epilogue: pack fp16 pairs -> g_op tile (mt, kt=h)
#pragma unroll
    for (int mi = 0; mi < 4; mi++)
#pragma unroll
        for (int ni = 0; ni < 2; ni++)
#pragma unroll
            for (int e2 = 0; e2 < 2; e2++) {
                int rl = wm + mi * 16 + g + e2 * 8;
                int lk = ((wn + ni * 8) >> 1) + t4;  // word col 0..31
                g_op[(mt * 16 + h) * 4096 + perm_word(4, rl, lk)] =
                    pk(oacc[mi][ni][e2 * 2], oacc[mi][ni][e2 * 2 + 1]);
            }

    // deterministic row-sum reduction (reuse Sp region)
    __syncthreads();
    float* rs = (float*)Sp;
    rs[tid] = 0.f;
    rs[tid + 256] = 0.f;
    __syncthreads();
#pragma unroll
    for (int mi = 0; mi < 4; mi++)
#pragma unroll
        for (int e2 = 0; e2 < 2; e2++) {
            float r = rsum[mi][e2];
            r += __shfl_xor_sync(0xffffffffu, r, 1);
            r += __shfl_xor_sync(0xffffffffu, r, 2);
            if (t4 == 0) rs[(wid >> 1) * 128 + wm + mi * 16 + g + e2 * 8] = r;
        }
    __syncthreads();
    if (tid < 128)
        g_rsum[h * SQ + m0 + tid] =
            rs[tid] + rs[128 + tid] + rs[256 + tid] + rs[384 + tid];
}

// ---------------------------------------------------------------------------
// Heterogeneous tail: blocks 0..127 = output projection (fp16 cp.async GEMM);
// blocks 128+ = attn scale stream, 4 rows in flight, no barriers.
// ---------------------------------------------------------------------------
__global__ __launch_bounds__(256, 2) void out_scale(float* __restrict__ C,
                                                    float* __restrict__ attn) {
    extern __shared__ uint32_t sm[];
    const int bid = blockIdx.x;
    const int tid = threadIdx.x;

    if (bid >= 128) {  // scale: 2048 blocks x 16 rows, 4 rows per iteration
        const int r0 = (bid - 128) * 16;
        for (int rr = 0; rr < 16; rr += 4) {
            float4 va[4], vb[4];
            float inv[4];
#pragma unroll
            for (int r = 0; r < 4; r++) {
                const int row = r0 + rr + r;
                inv[r] = 1.0f / g_rsum[row];
                const float* p = attn + (size_t)row * SQ;
                va[r] = __ldcs((const float4*)(p + tid * 4));
                vb[r] = __ldcs((const float4*)(p + 1024 + tid * 4));
            }
#pragma unroll
            for (int r = 0; r < 4; r++) {
                float* p = attn + (size_t)(r0 + rr + r) * SQ;
                va[r].x *= inv[r]; va[r].y *= inv[r];
                va[r].z *= inv[r]; va[r].w *= inv[r];
                vb[r].x *= inv[r]; vb[r].y *= inv[r];
                vb[r].z *= inv[r]; vb[r].w *= inv[r];
                __stcs((float4*)(p + tid * 4), va[r]);
                __stcs((float4*)(p + 1024 + tid * 4), vb[r]);
            }
        }
        return;
    }

    const int mt = bid >> 3, nt = bid & 7;
    const int lane = tid & 31, wid = tid >> 5;
    const int g = lane >> 2, t4 = lane & 3;
    const int wm = (wid & 1) * 64, wn = (wid >> 1) * 32;
    const uint32_t* At = g_op + (size_t)(mt * 16) * 4096;
    const uint32_t* Bt = g_wp + (size_t)(3 * 128 + nt * 16) * 4096;

#pragma unroll
    for (int i = 0; i < 4; i++) {
        cpa16(sm + tid * 4 + i * 1024, At + tid * 4 + i * 1024);
        cpa16(sm + 4096 + tid * 4 + i * 1024, Bt + tid * 4 + i * 1024);
    }
    CPA_COMMIT;

    float acc[4][4][4] = {};

    for (int kt = 0; kt < 16; kt++) {
        uint32_t* S = sm + (kt & 1) * 8192;
        CPA_WAIT(0);
        __syncthreads();
        if (kt + 1 < 16) {
            uint32_t* Nx = sm + ((kt + 1) & 1) * 8192;
            const uint32_t* An = At + (kt + 1) * 4096;
            const uint32_t* Bn = Bt + (kt + 1) * 4096;
#pragma unroll
            for (int i = 0; i < 4; i++) {
                cpa16(Nx + tid * 4 + i * 1024, An + tid * 4 + i * 1024);
                cpa16(Nx + 4096 + tid * 4 + i * 1024, Bn + tid * 4 + i * 1024);
            }
            CPA_COMMIT;
        }
#pragma unroll
        for (int s = 0; s < 4; s++) {
            uint4 av[4], bv[2];
#pragma unroll
            for (int mi = 0; mi < 4; mi++)
                av[mi] = *(const uint4*)&S[frag_addr(4, (wm >> 4) + mi, s, g, t4)];
#pragma unroll
            for (int bi = 0; bi < 2; bi++)
                bv[bi] = *(const uint4*)&S[4096 + frag_addr(4, (wn >> 4) + bi, s, g, t4)];
#pragma unroll
            for (int mi = 0; mi < 4; mi++)
#pragma unroll
                for (int bi = 0; bi < 2; bi++) {
                    mma16(acc[mi][bi * 2], av[mi].x, av[mi].y, av[mi].z, av[mi].w,
                          bv[bi].x, bv[bi].z);
                    mma16(acc[mi][bi * 2 + 1], av[mi].x, av[mi].y, av[mi].z, av[mi].w,
                          bv[bi].y, bv[bi].w);
                }
        }
    }

#pragma unroll
    for (int mi = 0; mi < 4; mi++)
#pragma unroll
        for (int ni = 0; ni < 4; ni++)
#pragma unroll
            for (int e = 0; e < 4; e++) {
                int row = mt * 128 + wm + mi * 16 + g + (e >> 1) * 8;
                int col = nt * 128 + wn + ni * 8 + t4 * 2 + (e & 1);
                C[(size_t)row * DM + col] = acc[mi][ni][e];
            }
}

extern "C" void kernel_launch(void* const* d_in, const int* in_sizes, int n_in,
                              void* d_out, int out_size) {
    const float* q_in = (const float*)d_in[0];
    const float* k_in = (const float*)d_in[1];
    const float* v_in = (const float*)d_in[2];
    const int* mask = (const int*)d_in[3];
    const float* Wq = (const float*)d_in[4];
    const float* Wk = (const float*)d_in[5];
    const float* Wv = (const float*)d_in[6];
    const float* Wo = (const float*)d_in[7];

    float* out = (float*)d_out;           // [S, DM]
    float* attn = out + (size_t)SQ * DM;  // [H, S, S]

    static int smem_set = 0;
    if (!smem_set) {
        cudaFuncSetAttribute(fused_attn, cudaFuncAttributeMaxDynamicSharedMemorySize,
                             65536);
        cudaFuncSetAttribute(gemm_qkv, cudaFuncAttributeMaxDynamicSharedMemorySize,
                             65536);
        cudaFuncSetAttribute(out_scale, cudaFuncAttributeMaxDynamicSharedMemorySize,
                             65536);
        smem_set = 1;
    }

    prep<<<1536, 256>>>(q_in, k_in, v_in, Wq, Wk, Wv, Wo, mask);

    dim3 gQKV(8, 16, 3);
    gemm_qkv<<<gQKV, 256, 65536>>>();

    dim3 gFused(SQ / 128, NH, 1);  // (16, 16)
    fused_attn<<<gFused, 256, 65536>>>(attn);

    out_scale<<<128 + 2048, 256, 65536>>>(out, attn);
}

// round 11
// speedup vs baseline: 2.5431x; 1.1333x over previous
#include <cuda_runtime.h>
#include <cuda_fp16.h>
#include <cstdint>

#define SQ 2048
#define DM 1024
#define NH 16
#define HD 64
#define NT (SQ / 64)  // 32 column tiles in fused

// All operand tensors stored as fp16x2 words (low half = even index).
__device__ float g_rsum[NH * SQ];            // per-row softmax denominators
__device__ uint32_t g_mbits[64 * SQ];        // mask bitmask, [wordcol][row]
__device__ uint32_t g_ap[3 * 256 * 4096];    // q,k,v inputs: permuted [z][mt][kt]
__device__ uint32_t g_wp[4 * 128 * 4096];    // Wq,Wk,Wv,Wo: permuted [w][nt][kt]
__device__ uint32_t g_op[256 * 4096];        // attention out O: permuted [mt][kt]
__device__ uint32_t g_qp[NH * 16 * 4096];    // Q proj (pre-scaled 1/8), per (h, mt)
__device__ uint32_t g_kp[NH * 32 * 2048];    // K proj, per (h, ttile)
__device__ uint32_t g_vp[NH * 32 * 2048];    // V^T proj, per (h, ttile)

__device__ __forceinline__ uint32_t pk(float a, float b) {
    __half2 h = __floats2half2_rn(a, b);
    return *reinterpret_cast<uint32_t*>(&h);
}

// m16n8k16 fp16 MMA, fp32 accumulate.
__device__ __forceinline__ void mma16(float* c, uint32_t a0, uint32_t a1, uint32_t a2,
                                      uint32_t a3, uint32_t b0, uint32_t b1) {
    asm("mma.sync.aligned.m16n8k16.row.col.f32.f16.f16.f32 "
        "{%0,%1,%2,%3},{%4,%5,%6,%7},{%8,%9},{%0,%1,%2,%3};"
        : "+f"(c[0]), "+f"(c[1]), "+f"(c[2]), "+f"(c[3])
        : "r"(a0), "r"(a1), "r"(a2), "r"(a3), "r"(b0), "r"(b1));
}

// Permuted fragment-major layout over 32-bit words (word = fp16 pair).
__device__ __forceinline__ int perm_word(int NS, int r, int k) {
    int gg = r & 7;
    int kk = k & 7;
    int L = gg * 4 + ((kk & 3) ^ (gg & 3));
    return (((r >> 4) * NS + (k >> 3)) * 32 + L) * 4 + ((r >> 3) & 1) + 2 * (kk >> 2);
}
__device__ __forceinline__ void sts_perm4(uint32_t* S, int NS, int r, int c4, uint4 u) {
    int gg = r & 7;
    int base = (((r >> 4) * NS + (c4 >> 3)) * 32 + gg * 4) * 4 + ((r >> 3) & 1) +
               2 * ((c4 >> 2) & 1);
    int x = gg & 3;
    S[base + (0 ^ x) * 4] = u.x;
    S[base + (1 ^ x) * 4] = u.y;
    S[base + (2 ^ x) * 4] = u.z;
    S[base + (3 ^ x) * 4] = u.w;
}
__device__ __forceinline__ int frag_addr(int NS, int band, int s, int g, int t4) {
    return ((band * NS + s) * 32 + g * 4 + (t4 ^ (g & 3))) * 4;
}

__device__ __forceinline__ void cpa16(void* dst, const void* src) {
    uint32_t s = (uint32_t)__cvta_generic_to_shared(dst);
    asm volatile("cp.async.cg.shared.global [%0], [%1], 16;" ::"r"(s), "l"(src));
}
#define CPA_COMMIT asm volatile("cp.async.commit_group;")
#define CPA_WAIT(n) asm volatile("cp.async.wait_group %0;" ::"n"(n))

// ---------------------------------------------------------------------------
// Pre-pass: fp16-convert + pre-permute activations (blocks 0..767) and weights
// (768..1279); mask bit-compaction (1280+).
// ---------------------------------------------------------------------------
__global__ __launch_bounds__(256) void prep(
    const float* __restrict__ q_in, const float* __restrict__ k_in,
    const float* __restrict__ v_in, const float* __restrict__ Wq,
    const float* __restrict__ Wk, const float* __restrict__ Wv,
    const float* __restrict__ Wo, const int* __restrict__ mask) {
    const int bid = blockIdx.x;
    const int tid = threadIdx.x;

    if (bid >= 1280) {  // mask compaction: 256 blocks x 8 rows (warp per row)
        const int lane = tid & 31, wid = tid >> 5;
        const int row = (bid - 1280) * 8 + wid;
        const int4* mp = (const int4*)(mask + (size_t)row * SQ + lane * 64);
        uint32_t w0 = 0, w1 = 0;
#pragma unroll
        for (int i = 0; i < 16; i++) {
            int4 m = mp[i];
            uint32_t bits = (m.x != 0 ? 1u : 0u) | (m.y != 0 ? 2u : 0u) |
                            (m.z != 0 ? 4u : 0u) | (m.w != 0 ? 8u : 0u);
            if (i < 8)
                w0 |= bits << (i * 4);
            else
                w1 |= bits << ((i - 8) * 4);
        }
        g_mbits[(lane * 2 + 0) * SQ + row] = w0;
        g_mbits[(lane * 2 + 1) * SQ + row] = w1;
        return;
    }

    __shared__ uint32_t sp[4096];
    const float* src;
    uint32_t* dst;
    int r0, c0;
    if (bid < 768) {  // activation tile: z(3), mt(16), kt(16)
        int z = bid >> 8, rem = bid & 255;
        src = z == 0 ? q_in : z == 1 ? k_in : v_in;
        r0 = (rem >> 4) * 128;
        c0 = (rem & 15) * 64;
        dst = g_ap + (size_t)bid * 4096;
    } else {  // weight tile: w(4), nt(8), kt(16)
        int wb = bid - 768;
        int w = wb >> 7, rem = wb & 127;
        src = w == 0 ? Wq : w == 1 ? Wk : w == 2 ? Wv : Wo;
        r0 = (rem >> 4) * 128;
        c0 = (rem & 15) * 64;
        dst = g_wp + (size_t)wb * 4096;
    }
#pragma unroll
    for (int i = 0; i < 4; i++) {
        int idx = tid + i * 256, r = idx >> 3, c4 = (idx & 7) * 4;  // word col
        const float* p = src + (size_t)(r0 + r) * DM + c0 + 2 * c4;
        float4 f0 = *(const float4*)p;
        float4 f1 = *(const float4*)(p + 4);
        uint4 u = {pk(f0.x, f0.y), pk(f0.z, f0.w), pk(f1.x, f1.y), pk(f1.z, f1.w)};
        sts_perm4(sp, 4, r, c4, u);
    }
    __syncthreads();
#pragma unroll
    for (int i = 0; i < 4; i++)
        *(uint4*)(dst + tid * 4 + i * 1024) = *(const uint4*)(sp + tid * 4 + i * 1024);
}

// ---------------------------------------------------------------------------
// QKV projection GEMMs (fp16). BM=128, BN=128, BK=64, cp.async double-buffered.
// Q pre-scaled by 1/8. V epilogue: smem-bounce transpose -> V^T t-pair packing.
// ---------------------------------------------------------------------------
__global__ __launch_bounds__(256, 2) void gemm_qkv() {
    extern __shared__ uint32_t sm[];  // 2 stages x (A 4096 | B 4096)
    const int z = blockIdx.z, mt = blockIdx.y, nt = blockIdx.x;
    const int tid = threadIdx.x, lane = tid & 31, wid = tid >> 5;
    const int g = lane >> 2, t4 = lane & 3;
    const int wm = (wid & 1) * 64, wn = (wid >> 1) * 32;
    const uint32_t* At = g_ap + (size_t)(z * 256 + mt * 16) * 4096;
    const uint32_t* Bt = g_wp + (size_t)(z * 128 + nt * 16) * 4096;

#pragma unroll
    for (int i = 0; i < 4; i++) {
        cpa16(sm + tid * 4 + i * 1024, At + tid * 4 + i * 1024);
        cpa16(sm + 4096 + tid * 4 + i * 1024, Bt + tid * 4 + i * 1024);
    }
    CPA_COMMIT;

    float acc[4][4][4] = {};

    for (int kt = 0; kt < 16; kt++) {
        uint32_t* S = sm + (kt & 1) * 8192;
        CPA_WAIT(0);
        __syncthreads();
        if (kt + 1 < 16) {
            uint32_t* Nx = sm + ((kt + 1) & 1) * 8192;
            const uint32_t* An = At + (kt + 1) * 4096;
            const uint32_t* Bn = Bt + (kt + 1) * 4096;
#pragma unroll
            for (int i = 0; i < 4; i++) {
                cpa16(Nx + tid * 4 + i * 1024, An + tid * 4 + i * 1024);
                cpa16(Nx + 4096 + tid * 4 + i * 1024, Bn + tid * 4 + i * 1024);
            }
            CPA_COMMIT;
        }
#pragma unroll
        for (int s = 0; s < 4; s++) {
            uint4 av[4], bv[2];
#pragma unroll
            for (int mi = 0; mi < 4; mi++)
                av[mi] = *(const uint4*)&S[frag_addr(4, (wm >> 4) + mi, s, g, t4)];
#pragma unroll
            for (int bi = 0; bi < 2; bi++)
                bv[bi] = *(const uint4*)&S[4096 + frag_addr(4, (wn >> 4) + bi, s, g, t4)];
#pragma unroll
            for (int mi = 0; mi < 4; mi++)
#pragma unroll
                for (int bi = 0; bi < 2; bi++) {
                    mma16(acc[mi][bi * 2], av[mi].x, av[mi].y, av[mi].z, av[mi].w,
                          bv[bi].x, bv[bi].z);
                    mma16(acc[mi][bi * 2 + 1], av[mi].x, av[mi].y, av[mi].z, av[mi].w,
                          bv[bi].y, bv[bi].w);
                }
        }
    }

    if (z < 2) {
        const float sc = (z == 0) ? 0.125f : 1.0f;
#pragma unroll
        for (int mi = 0; mi < 4; mi++)
#pragma unroll
            for (int ni = 0; ni < 4; ni++) {
                int row = wm + mi * 16 + g;
                int colp = wn + ni * 8 + 2 * t4;
                int gn = nt * 128 + colp;
                int h = gn >> 6, kkw = (gn & 63) >> 1;
                uint32_t w0 = pk(acc[mi][ni][0] * sc, acc[mi][ni][1] * sc);
                uint32_t w1 = pk(acc[mi][ni][2] * sc, acc[mi][ni][3] * sc);
                if (z == 0) {
                    g_qp[(h * 16 + mt) * 4096 + perm_word(4, row, kkw)] = w0;
                    g_qp[(h * 16 + mt) * 4096 + perm_word(4, row + 8, kkw)] = w1;
                } else {
                    int tile = mt * 2 + (row >> 6);
                    int r64 = row & 63;
                    g_kp[(h * 32 + tile) * 2048 + perm_word(4, r64, kkw)] = w0;
                    g_kp[(h * 32 + tile) * 2048 + perm_word(4, r64 + 8, kkw)] = w1;
                }
            }
    } else {
        // V: bounce through smem, transpose, pack t-pairs -> g_vp (V^T)
        __syncthreads();
        __half* hb = (__half*)sm;  // [128 rows][130 halves]
#pragma unroll
        for (int mi = 0; mi < 4; mi++)
#pragma unroll
            for (int ni = 0; ni < 4; ni++) {
                int row = wm + mi * 16 + g;
                int colw = ((wn + ni * 8) >> 1) + t4;
                *(uint32_t*)&hb[row * 130 + 2 * colw] =
                    pk(acc[mi][ni][0], acc[mi][ni][1]);
                *(uint32_t*)&hb[(row + 8) * 130 + 2 * colw] =
                    pk(acc[mi][ni][2], acc[mi][ni][3]);
            }
        __syncthreads();
#pragma unroll
        for (int i = 0; i < 32; i++) {
            int widx = tid + i * 256;
            int dl = widx >> 6;
            int tw = widx & 63;
            __half lo = hb[(2 * tw) * 130 + dl];
            __half hi = hb[(2 * tw + 1) * 130 + dl];
            __half2 hh = __halves2half2(lo, hi);
            int gd = nt * 128 + dl;
            int h = gd >> 6, dr = gd & 63;
            int tt = mt * 2 + (tw >> 5), tkk = tw & 31;
            g_vp[(h * 32 + tt) * 2048 + perm_word(4, dr, tkk)] = *(uint32_t*)&hh;
        }
    }
}

// ---------------------------------------------------------------------------
// Fused attention, M-split warps (each warp owns 16 rows x full 64-col stripe).
// S C-fragments repack in registers into AV A-fragments: no Sp smem, ONE sync
// per tile. Q fragments hoisted (loop-invariant). Row sums reduce via shfl
// over t4 only (each row owned by one warp) -> direct g_rsum store.
// smem: Qp 16K | Kp 2x8K | Vp 2x8K = 48KB.
// ---------------------------------------------------------------------------
__global__ __launch_bounds__(256, 2) void fused_attn(float* __restrict__ attn) {
    extern __shared__ uint32_t sm[];
    uint32_t* Qp = sm;           // 4096 w
    uint32_t* Kp = sm + 4096;    // 2 x 2048 w
    uint32_t* Vp = sm + 8192;    // 2 x 2048 w

    const int tid = threadIdx.x, lane = tid & 31, wid = tid >> 5;
    const int g = lane >> 2, t4 = lane & 3;
    const int h = blockIdx.y, mt = blockIdx.x;
    const int m0 = mt * 128;
    const int r0 = wid * 16 + g;  // this thread's first row (block-local)
    const size_t attn_base = (size_t)h * SQ * SQ;
    const uint32_t* kg = g_kp + h * 32 * 2048;
    const uint32_t* vg = g_vp + h * 32 * 2048;

    // prologue: cp.async Q, K[0], V[0]
    {
        const uint32_t* qg = g_qp + (h * 16 + mt) * 4096;
#pragma unroll
        for (int i = 0; i < 4; i++)
            cpa16(Qp + tid * 4 + i * 1024, qg + tid * 4 + i * 1024);
    }
#pragma unroll
    for (int i = 0; i < 2; i++) {
        cpa16(Kp + tid * 4 + i * 1024, kg + tid * 4 + i * 1024);
        cpa16(Vp + tid * 4 + i * 1024, vg + tid * 4 + i * 1024);
    }
    CPA_COMMIT;
    CPA_WAIT(0);
    __syncthreads();

    // hoist Q fragments (loop-invariant): warp band = wid
    uint4 qf[4];
#pragma unroll
    for (int s = 0; s < 4; s++)
        qf[s] = *(const uint4*)&Qp[frag_addr(4, wid, s, g, t4)];

    float oacc[8][4] = {};
    float rsum[2] = {};

    for (int tt = 0; tt < NT; tt++) {
        const int t0 = tt * 64;
        uint32_t* Kc = Kp + (tt & 1) * 2048;
        uint32_t* Vc = Vp + (tt & 1) * 2048;

        // mask bits: 2 rows x 2 words (L2 hits)
        uint32_t mw[2][2];
        {
            const uint32_t* mb = g_mbits + (size_t)(tt * 2) * SQ + m0;
            mw[0][0] = mb[r0];
            mw[0][1] = mb[SQ + r0];
            mw[1][0] = mb[r0 + 8];
            mw[1][1] = mb[SQ + r0 + 8];
        }

        if (tt + 1 < NT) {  // prefetch next K,V into the other buffer
            uint32_t* Kn = Kp + ((tt + 1) & 1) * 2048;
            uint32_t* Vn = Vp + ((tt + 1) & 1) * 2048;
#pragma unroll
            for (int i = 0; i < 2; i++) {
                cpa16(Kn + tid * 4 + i * 1024,
                      kg + (tt + 1) * 2048 + tid * 4 + i * 1024);
                cpa16(Vn + tid * 4 + i * 1024,
                      vg + (tt + 1) * 2048 + tid * 4 + i * 1024);
            }
            CPA_COMMIT;
        }

        // S = (Q/8) K^T : 16 rows x 64 cols per warp
        float sacc[8][4] = {};
#pragma unroll
        for (int s = 0; s < 4; s++) {
#pragma unroll
            for (int b = 0; b < 4; b++) {
                uint4 bk = *(const uint4*)&Kc[frag_addr(4, b, s, g, t4)];
                mma16(sacc[b * 2], qf[s].x, qf[s].y, qf[s].z, qf[s].w, bk.x, bk.z);
                mma16(sacc[b * 2 + 1], qf[s].x, qf[s].y, qf[s].z, qf[s].w, bk.y, bk.w);
            }
        }

        // epilogue: mask; attn <- exp(v); rsum; repack masked v -> AV A-frags
        uint4 av[4];
#pragma unroll
        for (int ni = 0; ni < 8; ni++) {
            int cl = ni * 8 + 2 * t4;
            int word = ni >> 2, bit = cl & 31;
            float v00 = sacc[ni][0], v01 = sacc[ni][1];  // row r0
            float v10 = sacc[ni][2], v11 = sacc[ni][3];  // row r0+8
            uint32_t w0 = mw[0][word], w1 = mw[1][word];
            if ((w0 >> bit) & 1) v00 = -1e-7f;
            if ((w0 >> (bit + 1)) & 1) v01 = -1e-7f;
            if ((w1 >> bit) & 1) v10 = -1e-7f;
            if ((w1 >> (bit + 1)) & 1) v11 = -1e-7f;
            float e00 = __expf(v00), e01 = __expf(v01);
            float e10 = __expf(v10), e11 = __expf(v11);
            size_t cg = attn_base + (size_t)(m0 + r0) * SQ + t0 + cl;
            __stcs((float2*)(attn + cg), make_float2(e00, e01));
            __stcs((float2*)(attn + cg + 8 * SQ), make_float2(e10, e11));
            rsum[0] += e00 + e01;
            rsum[1] += e10 + e11;
            uint32_t plo = pk(v00, v01), phi = pk(v10, v11);
            if ((ni & 1) == 0) {
                av[ni >> 1].x = plo;
                av[ni >> 1].y = phi;
            } else {
                av[ni >> 1].z = plo;
                av[ni >> 1].w = phi;
            }
        }

        // O += S @ V (A-frags from registers, B from Vp)
#pragma unroll
        for (int s = 0; s < 4; s++) {
#pragma unroll
            for (int b = 0; b < 4; b++) {
                uint4 bv = *(const uint4*)&Vc[frag_addr(4, b, s, g, t4)];
                mma16(oacc[b * 2], av[s].x, av[s].y, av[s].z, av[s].w, bv.x, bv.z);
                mma16(oacc[b * 2 + 1], av[s].x, av[s].y, av[s].z, av[s].w, bv.y, bv.w);
            }
        }

        if (tt + 1 < NT) {
            CPA_WAIT(0);      // next K,V landed
            __syncthreads();  // all warps done with current buffers
        }
    }

    // O epilogue: pack fp16 pairs -> g_op tile (mt, kt=h)
#pragma unroll
    for (int di = 0; di < 8; di++) {
        int lk = di * 4 + t4;  // word col 0..31
        g_op[(mt * 16 + h) * 4096 + perm_word(4, r0, lk)] =
            pk(oacc[di][0], oacc[di][1]);
        g_op[(mt * 16 + h) * 4096 + perm_word(4, r0 + 8, lk)] =
            pk(oacc[di][2], oacc[di][3]);
    }

    // row sums: reduce over t4 lanes only (row owned by this warp)
    rsum[0] += __shfl_xor_sync(0xffffffffu, rsum[0], 1);
    rsum[0] += __shfl_xor_sync(0xffffffffu, rsum[0], 2);
    rsum[1] += __shfl_xor_sync(0xffffffffu, rsum[1], 1);
    rsum[1] += __shfl_xor_sync(0xffffffffu, rsum[1], 2);
    if (t4 == 0) {
        g_rsum[h * SQ + m0 + r0] = rsum[0];
        g_rsum[h * SQ + m0 + r0 + 8] = rsum[1];
    }
}

// ---------------------------------------------------------------------------
// Heterogeneous tail: blocks 0..127 = output projection (fp16 cp.async GEMM);
// blocks 128+ = attn scale stream, 4 rows in flight, no barriers.
// ---------------------------------------------------------------------------
__global__ __launch_bounds__(256, 2) void out_scale(float* __restrict__ C,
                                                    float* __restrict__ attn) {
    extern __shared__ uint32_t sm[];
    const int bid = blockIdx.x;
    const int tid = threadIdx.x;

    if (bid >= 128) {  // scale: 2048 blocks x 16 rows, 4 rows per iteration
        const int r0 = (bid - 128) * 16;
        for (int rr = 0; rr < 16; rr += 4) {
            float4 va[4], vb[4];
            float inv[4];
#pragma unroll
            for (int r = 0; r < 4; r++) {
                const int row = r0 + rr + r;
                inv[r] = 1.0f / g_rsum[row];
                const float* p = attn + (size_t)row * SQ;
                va[r] = __ldcs((const float4*)(p + tid * 4));
                vb[r] = __ldcs((const float4*)(p + 1024 + tid * 4));
            }
#pragma unroll
            for (int r = 0; r < 4; r++) {
                float* p = attn + (size_t)(r0 + rr + r) * SQ;
                va[r].x *= inv[r]; va[r].y *= inv[r];
                va[r].z *= inv[r]; va[r].w *= inv[r];
                vb[r].x *= inv[r]; vb[r].y *= inv[r];
                vb[r].z *= inv[r]; vb[r].w *= inv[r];
                __stcs((float4*)(p + tid * 4), va[r]);
                __stcs((float4*)(p + 1024 + tid * 4), vb[r]);
            }
        }
        return;
    }

    const int mt = bid >> 3, nt = bid & 7;
    const int lane = tid & 31, wid = tid >> 5;
    const int g = lane >> 2, t4 = lane & 3;
    const int wm = (wid & 1) * 64, wn = (wid >> 1) * 32;
    const uint32_t* At = g_op + (size_t)(mt * 16) * 4096;
    const uint32_t* Bt = g_wp + (size_t)(3 * 128 + nt * 16) * 4096;

#pragma unroll
    for (int i = 0; i < 4; i++) {
        cpa16(sm + tid * 4 + i * 1024, At + tid * 4 + i * 1024);
        cpa16(sm + 4096 + tid * 4 + i * 1024, Bt + tid * 4 + i * 1024);
    }
    CPA_COMMIT;

    float acc[4][4][4] = {};

    for (int kt = 0; kt < 16; kt++) {
        uint32_t* S = sm + (kt & 1) * 8192;
        CPA_WAIT(0);
        __syncthreads();
        if (kt + 1 < 16) {
            uint32_t* Nx = sm + ((kt + 1) & 1) * 8192;
            const uint32_t* An = At + (kt + 1) * 4096;
            const uint32_t* Bn = Bt + (kt + 1) * 4096;
#pragma unroll
            for (int i = 0; i < 4; i++) {
                cpa16(Nx + tid * 4 + i * 1024, An + tid * 4 + i * 1024);
                cpa16(Nx + 4096 + tid * 4 + i * 1024, Bn + tid * 4 + i * 1024);
            }
            CPA_COMMIT;
        }
#pragma unroll
        for (int s = 0; s < 4; s++) {
            uint4 av[4], bv[2];
#pragma unroll
            for (int mi = 0; mi < 4; mi++)
                av[mi] = *(const uint4*)&S[frag_addr(4, (wm >> 4) + mi, s, g, t4)];
#pragma unroll
            for (int bi = 0; bi < 2; bi++)
                bv[bi] = *(const uint4*)&S[4096 + frag_addr(4, (wn >> 4) + bi, s, g, t4)];
#pragma unroll
            for (int mi = 0; mi < 4; mi++)
#pragma unroll
                for (int bi = 0; bi < 2; bi++) {
                    mma16(acc[mi][bi * 2], av[mi].x, av[mi].y, av[mi].z, av[mi].w,
                          bv[bi].x, bv[bi].z);
                    mma16(acc[mi][bi * 2 + 1], av[mi].x, av[mi].y, av[mi].z, av[mi].w,
                          bv[bi].y, bv[bi].w);
                }
        }
    }

#pragma unroll
    for (int mi = 0; mi < 4; mi++)
#pragma unroll
        for (int ni = 0; ni < 4; ni++)
#pragma unroll
            for (int e = 0; e < 4; e++) {
                int row = mt * 128 + wm + mi * 16 + g + (e >> 1) * 8;
                int col = nt * 128 + wn + ni * 8 + t4 * 2 + (e & 1);
                C[(size_t)row * DM + col] = acc[mi][ni][e];
            }
}

extern "C" void kernel_launch(void* const* d_in, const int* in_sizes, int n_in,
                              void* d_out, int out_size) {
    const float* q_in = (const float*)d_in[0];
    const float* k_in = (const float*)d_in[1];
    const float* v_in = (const float*)d_in[2];
    const int* mask = (const int*)d_in[3];
    const float* Wq = (const float*)d_in[4];
    const float* Wk = (const float*)d_in[5];
    const float* Wv = (const float*)d_in[6];
    const float* Wo = (const float*)d_in[7];

    float* out = (float*)d_out;           // [S, DM]
    float* attn = out + (size_t)SQ * DM;  // [H, S, S]

    static int smem_set = 0;
    if (!smem_set) {
        cudaFuncSetAttribute(fused_attn, cudaFuncAttributeMaxDynamicSharedMemorySize,
                             49152);
        cudaFuncSetAttribute(gemm_qkv, cudaFuncAttributeMaxDynamicSharedMemorySize,
                             65536);
        cudaFuncSetAttribute(out_scale, cudaFuncAttributeMaxDynamicSharedMemorySize,
                             65536);
        smem_set = 1;
    }

    prep<<<1536, 256>>>(q_in, k_in, v_in, Wq, Wk, Wv, Wo, mask);

    dim3 gQKV(8, 16, 3);
    gemm_qkv<<<gQKV, 256, 65536>>>();

    dim3 gFused(SQ / 128, NH, 1);  // (16, 16)
    fused_attn<<<gFused, 256, 49152>>>(attn);

    out_scale<<<128 + 2048, 256, 65536>>>(out, attn);
}

// round 12
// speedup vs baseline: 2.7890x; 1.0967x over previous
#include <cuda_runtime.h>
#include <cuda_fp16.h>
#include <cstdint>

#define SQ 2048
#define DM 1024
#define NH 16
#define HD 64
#define NT (SQ / 64)  // 32 column tiles

// All operand tensors stored as fp16x2 words (low half = even index).
__device__ float g_rsum[NH * SQ];            // per-row softmax denominators
__device__ uint32_t g_mbits[64 * SQ];        // mask bitmask, [wordcol][row]
__device__ uint32_t g_ap[3 * 256 * 4096];    // q,k,v inputs: permuted [z][mt][kt]
__device__ uint32_t g_wp[4 * 128 * 4096];    // Wq,Wk,Wv,Wo: permuted [w][nt][kt]
__device__ uint32_t g_op[256 * 4096];        // attention out O: permuted [mt][kt]
__device__ uint32_t g_qp[NH * 16 * 4096];    // Q proj (pre-scaled 1/8), per (h, mt)
__device__ uint32_t g_kp[NH * 32 * 2048];    // K proj, per (h, ttile)
__device__ uint32_t g_vp[NH * 32 * 2048];    // V^T proj, per (h, ttile)

__device__ __forceinline__ uint32_t pk(float a, float b) {
    __half2 h = __floats2half2_rn(a, b);
    return *reinterpret_cast<uint32_t*>(&h);
}

__device__ __forceinline__ void mma16(float* c, uint32_t a0, uint32_t a1, uint32_t a2,
                                      uint32_t a3, uint32_t b0, uint32_t b1) {
    asm("mma.sync.aligned.m16n8k16.row.col.f32.f16.f16.f32 "
        "{%0,%1,%2,%3},{%4,%5,%6,%7},{%8,%9},{%0,%1,%2,%3};"
        : "+f"(c[0]), "+f"(c[1]), "+f"(c[2]), "+f"(c[3])
        : "r"(a0), "r"(a1), "r"(a2), "r"(a3), "r"(b0), "r"(b1));
}

// Permuted fragment-major layout over 32-bit words (word = fp16 pair).
__device__ __forceinline__ int perm_word(int NS, int r, int k) {
    int gg = r & 7;
    int kk = k & 7;
    int L = gg * 4 + ((kk & 3) ^ (gg & 3));
    return (((r >> 4) * NS + (k >> 3)) * 32 + L) * 4 + ((r >> 3) & 1) + 2 * (kk >> 2);
}
__device__ __forceinline__ void sts_perm4(uint32_t* S, int NS, int r, int c4, uint4 u) {
    int gg = r & 7;
    int base = (((r >> 4) * NS + (c4 >> 3)) * 32 + gg * 4) * 4 + ((r >> 3) & 1) +
               2 * ((c4 >> 2) & 1);
    int x = gg & 3;
    S[base + (0 ^ x) * 4] = u.x;
    S[base + (1 ^ x) * 4] = u.y;
    S[base + (2 ^ x) * 4] = u.z;
    S[base + (3 ^ x) * 4] = u.w;
}
__device__ __forceinline__ int frag_addr(int NS, int band, int s, int g, int t4) {
    return ((band * NS + s) * 32 + g * 4 + (t4 ^ (g & 3))) * 4;
}

__device__ __forceinline__ void cpa16(void* dst, const void* src) {
    uint32_t s = (uint32_t)__cvta_generic_to_shared(dst);
    asm volatile("cp.async.cg.shared.global [%0], [%1], 16;" ::"r"(s), "l"(src));
}
#define CPA_COMMIT asm volatile("cp.async.commit_group;")
#define CPA_WAIT(n) asm volatile("cp.async.wait_group %0;" ::"n"(n))

// ---------------------------------------------------------------------------
// Pre-pass: fp16-convert + pre-permute activations (0..767) / weights
// (768..1279); mask bit-compaction (1280+).
// ---------------------------------------------------------------------------
__global__ __launch_bounds__(256) void prep(
    const float* __restrict__ q_in, const float* __restrict__ k_in,
    const float* __restrict__ v_in, const float* __restrict__ Wq,
    const float* __restrict__ Wk, const float* __restrict__ Wv,
    const float* __restrict__ Wo, const int* __restrict__ mask) {
    const int bid = blockIdx.x;
    const int tid = threadIdx.x;

    if (bid >= 1280) {
        const int lane = tid & 31, wid = tid >> 5;
        const int row = (bid - 1280) * 8 + wid;
        const int4* mp = (const int4*)(mask + (size_t)row * SQ + lane * 64);
        uint32_t w0 = 0, w1 = 0;
#pragma unroll
        for (int i = 0; i < 16; i++) {
            int4 m = mp[i];
            uint32_t bits = (m.x != 0 ? 1u : 0u) | (m.y != 0 ? 2u : 0u) |
                            (m.z != 0 ? 4u : 0u) | (m.w != 0 ? 8u : 0u);
            if (i < 8)
                w0 |= bits << (i * 4);
            else
                w1 |= bits << ((i - 8) * 4);
        }
        g_mbits[(lane * 2 + 0) * SQ + row] = w0;
        g_mbits[(lane * 2 + 1) * SQ + row] = w1;
        return;
    }

    __shared__ uint32_t sp[4096];
    const float* src;
    uint32_t* dst;
    int r0, c0;
    if (bid < 768) {
        int z = bid >> 8, rem = bid & 255;
        src = z == 0 ? q_in : z == 1 ? k_in : v_in;
        r0 = (rem >> 4) * 128;
        c0 = (rem & 15) * 64;
        dst = g_ap + (size_t)bid * 4096;
    } else {
        int wb = bid - 768;
        int w = wb >> 7, rem = wb & 127;
        src = w == 0 ? Wq : w == 1 ? Wk : w == 2 ? Wv : Wo;
        r0 = (rem >> 4) * 128;
        c0 = (rem & 15) * 64;
        dst = g_wp + (size_t)wb * 4096;
    }
#pragma unroll
    for (int i = 0; i < 4; i++) {
        int idx = tid + i * 256, r = idx >> 3, c4 = (idx & 7) * 4;
        const float* p = src + (size_t)(r0 + r) * DM + c0 + 2 * c4;
        float4 f0 = *(const float4*)p;
        float4 f1 = *(const float4*)(p + 4);
        uint4 u = {pk(f0.x, f0.y), pk(f0.z, f0.w), pk(f1.x, f1.y), pk(f1.z, f1.w)};
        sts_perm4(sp, 4, r, c4, u);
    }
    __syncthreads();
#pragma unroll
    for (int i = 0; i < 4; i++)
        *(uint4*)(dst + tid * 4 + i * 1024) = *(const uint4*)(sp + tid * 4 + i * 1024);
}

// ---------------------------------------------------------------------------
// QKV projection GEMMs (fp16). Q pre-scaled by 1/8. V -> V^T via smem bounce.
// ---------------------------------------------------------------------------
__global__ __launch_bounds__(256, 2) void gemm_qkv() {
    extern __shared__ uint32_t sm[];
    const int z = blockIdx.z, mt = blockIdx.y, nt = blockIdx.x;
    const int tid = threadIdx.x, lane = tid & 31, wid = tid >> 5;
    const int g = lane >> 2, t4 = lane & 3;
    const int wm = (wid & 1) * 64, wn = (wid >> 1) * 32;
    const uint32_t* At = g_ap + (size_t)(z * 256 + mt * 16) * 4096;
    const uint32_t* Bt = g_wp + (size_t)(z * 128 + nt * 16) * 4096;

#pragma unroll
    for (int i = 0; i < 4; i++) {
        cpa16(sm + tid * 4 + i * 1024, At + tid * 4 + i * 1024);
        cpa16(sm + 4096 + tid * 4 + i * 1024, Bt + tid * 4 + i * 1024);
    }
    CPA_COMMIT;

    float acc[4][4][4] = {};

    for (int kt = 0; kt < 16; kt++) {
        uint32_t* S = sm + (kt & 1) * 8192;
        CPA_WAIT(0);
        __syncthreads();
        if (kt + 1 < 16) {
            uint32_t* Nx = sm + ((kt + 1) & 1) * 8192;
            const uint32_t* An = At + (kt + 1) * 4096;
            const uint32_t* Bn = Bt + (kt + 1) * 4096;
#pragma unroll
            for (int i = 0; i < 4; i++) {
                cpa16(Nx + tid * 4 + i * 1024, An + tid * 4 + i * 1024);
                cpa16(Nx + 4096 + tid * 4 + i * 1024, Bn + tid * 4 + i * 1024);
            }
            CPA_COMMIT;
        }
#pragma unroll
        for (int s = 0; s < 4; s++) {
            uint4 av[4], bv[2];
#pragma unroll
            for (int mi = 0; mi < 4; mi++)
                av[mi] = *(const uint4*)&S[frag_addr(4, (wm >> 4) + mi, s, g, t4)];
#pragma unroll
            for (int bi = 0; bi < 2; bi++)
                bv[bi] = *(const uint4*)&S[4096 + frag_addr(4, (wn >> 4) + bi, s, g, t4)];
#pragma unroll
            for (int mi = 0; mi < 4; mi++)
#pragma unroll
                for (int bi = 0; bi < 2; bi++) {
                    mma16(acc[mi][bi * 2], av[mi].x, av[mi].y, av[mi].z, av[mi].w,
                          bv[bi].x, bv[bi].z);
                    mma16(acc[mi][bi * 2 + 1], av[mi].x, av[mi].y, av[mi].z, av[mi].w,
                          bv[bi].y, bv[bi].w);
                }
        }
    }

    if (z < 2) {
        const float sc = (z == 0) ? 0.125f : 1.0f;
#pragma unroll
        for (int mi = 0; mi < 4; mi++)
#pragma unroll
            for (int ni = 0; ni < 4; ni++) {
                int row = wm + mi * 16 + g;
                int colp = wn + ni * 8 + 2 * t4;
                int gn = nt * 128 + colp;
                int h = gn >> 6, kkw = (gn & 63) >> 1;
                uint32_t w0 = pk(acc[mi][ni][0] * sc, acc[mi][ni][1] * sc);
                uint32_t w1 = pk(acc[mi][ni][2] * sc, acc[mi][ni][3] * sc);
                if (z == 0) {
                    g_qp[(h * 16 + mt) * 4096 + perm_word(4, row, kkw)] = w0;
                    g_qp[(h * 16 + mt) * 4096 + perm_word(4, row + 8, kkw)] = w1;
                } else {
                    int tile = mt * 2 + (row >> 6);
                    int r64 = row & 63;
                    g_kp[(h * 32 + tile) * 2048 + perm_word(4, r64, kkw)] = w0;
                    g_kp[(h * 32 + tile) * 2048 + perm_word(4, r64 + 8, kkw)] = w1;
                }
            }
    } else {
        __syncthreads();
        __half* hb = (__half*)sm;  // [128 rows][130 halves]
#pragma unroll
        for (int mi = 0; mi < 4; mi++)
#pragma unroll
            for (int ni = 0; ni < 4; ni++) {
                int row = wm + mi * 16 + g;
                int colw = ((wn + ni * 8) >> 1) + t4;
                *(uint32_t*)&hb[row * 130 + 2 * colw] =
                    pk(acc[mi][ni][0], acc[mi][ni][1]);
                *(uint32_t*)&hb[(row + 8) * 130 + 2 * colw] =
                    pk(acc[mi][ni][2], acc[mi][ni][3]);
            }
        __syncthreads();
#pragma unroll
        for (int i = 0; i < 32; i++) {
            int widx = tid + i * 256;
            int dl = widx >> 6;
            int tw = widx & 63;
            __half lo = hb[(2 * tw) * 130 + dl];
            __half hi = hb[(2 * tw + 1) * 130 + dl];
            __half2 hh = __halves2half2(lo, hi);
            int gd = nt * 128 + dl;
            int h = gd >> 6, dr = gd & 63;
            int tt = mt * 2 + (tw >> 5), tkk = tw & 31;
            g_vp[(h * 32 + tt) * 2048 + perm_word(4, dr, tkk)] = *(uint32_t*)&hh;
        }
    }
}

// ---------------------------------------------------------------------------
// Pass 1: S = (Q/8)K^T, mask, exp -> rsum; O += S@V (pre-softmax S, register
// repack); O -> g_op; rsum -> g_rsum. NO attn stores.
// smem: Qp 16K | Kp 2x8K | Vp 2x8K = 48KB.
// ---------------------------------------------------------------------------
__global__ __launch_bounds__(256, 2) void fused_pass1() {
    extern __shared__ uint32_t sm[];
    uint32_t* Qp = sm;           // 4096 w
    uint32_t* Kp = sm + 4096;    // 2 x 2048 w
    uint32_t* Vp = sm + 8192;    // 2 x 2048 w

    const int tid = threadIdx.x, lane = tid & 31, wid = tid >> 5;
    const int g = lane >> 2, t4 = lane & 3;
    const int h = blockIdx.y, mt = blockIdx.x;
    const int m0 = mt * 128;
    const int r0 = wid * 16 + g;
    const uint32_t* kg = g_kp + h * 32 * 2048;
    const uint32_t* vg = g_vp + h * 32 * 2048;

    {
        const uint32_t* qg = g_qp + (h * 16 + mt) * 4096;
#pragma unroll
        for (int i = 0; i < 4; i++)
            cpa16(Qp + tid * 4 + i * 1024, qg + tid * 4 + i * 1024);
    }
#pragma unroll
    for (int i = 0; i < 2; i++) {
        cpa16(Kp + tid * 4 + i * 1024, kg + tid * 4 + i * 1024);
        cpa16(Vp + tid * 4 + i * 1024, vg + tid * 4 + i * 1024);
    }
    CPA_COMMIT;
    CPA_WAIT(0);
    __syncthreads();

    uint4 qf[4];
#pragma unroll
    for (int s = 0; s < 4; s++)
        qf[s] = *(const uint4*)&Qp[frag_addr(4, wid, s, g, t4)];

    float oacc[8][4] = {};
    float rsum[2] = {};

    for (int tt = 0; tt < NT; tt++) {
        uint32_t* Kc = Kp + (tt & 1) * 2048;
        uint32_t* Vc = Vp + (tt & 1) * 2048;

        uint32_t mw[2][2];
        {
            const uint32_t* mb = g_mbits + (size_t)(tt * 2) * SQ + m0;
            mw[0][0] = mb[r0];
            mw[0][1] = mb[SQ + r0];
            mw[1][0] = mb[r0 + 8];
            mw[1][1] = mb[SQ + r0 + 8];
        }

        if (tt + 1 < NT) {
            uint32_t* Kn = Kp + ((tt + 1) & 1) * 2048;
            uint32_t* Vn = Vp + ((tt + 1) & 1) * 2048;
#pragma unroll
            for (int i = 0; i < 2; i++) {
                cpa16(Kn + tid * 4 + i * 1024,
                      kg + (tt + 1) * 2048 + tid * 4 + i * 1024);
                cpa16(Vn + tid * 4 + i * 1024,
                      vg + (tt + 1) * 2048 + tid * 4 + i * 1024);
            }
            CPA_COMMIT;
        }

        float sacc[8][4] = {};
#pragma unroll
        for (int s = 0; s < 4; s++) {
#pragma unroll
            for (int b = 0; b < 4; b++) {
                uint4 bk = *(const uint4*)&Kc[frag_addr(4, b, s, g, t4)];
                mma16(sacc[b * 2], qf[s].x, qf[s].y, qf[s].z, qf[s].w, bk.x, bk.z);
                mma16(sacc[b * 2 + 1], qf[s].x, qf[s].y, qf[s].z, qf[s].w, bk.y, bk.w);
            }
        }

        uint4 av[4];
#pragma unroll
        for (int ni = 0; ni < 8; ni++) {
            int cl = ni * 8 + 2 * t4;
            int word = ni >> 2, bit = cl & 31;
            float v00 = sacc[ni][0], v01 = sacc[ni][1];
            float v10 = sacc[ni][2], v11 = sacc[ni][3];
            uint32_t w0 = mw[0][word], w1 = mw[1][word];
            if ((w0 >> bit) & 1) v00 = -1e-7f;
            if ((w0 >> (bit + 1)) & 1) v01 = -1e-7f;
            if ((w1 >> bit) & 1) v10 = -1e-7f;
            if ((w1 >> (bit + 1)) & 1) v11 = -1e-7f;
            rsum[0] += __expf(v00) + __expf(v01);
            rsum[1] += __expf(v10) + __expf(v11);
            uint32_t plo = pk(v00, v01), phi = pk(v10, v11);
            if ((ni & 1) == 0) {
                av[ni >> 1].x = plo;
                av[ni >> 1].y = phi;
            } else {
                av[ni >> 1].z = plo;
                av[ni >> 1].w = phi;
            }
        }

#pragma unroll
        for (int s = 0; s < 4; s++) {
#pragma unroll
            for (int b = 0; b < 4; b++) {
                uint4 bv = *(const uint4*)&Vc[frag_addr(4, b, s, g, t4)];
                mma16(oacc[b * 2], av[s].x, av[s].y, av[s].z, av[s].w, bv.x, bv.z);
                mma16(oacc[b * 2 + 1], av[s].x, av[s].y, av[s].z, av[s].w, bv.y, bv.w);
            }
        }

        if (tt + 1 < NT) {
            CPA_WAIT(0);
            __syncthreads();
        }
    }

#pragma unroll
    for (int di = 0; di < 8; di++) {
        int lk = di * 4 + t4;
        g_op[(mt * 16 + h) * 4096 + perm_word(4, r0, lk)] =
            pk(oacc[di][0], oacc[di][1]);
        g_op[(mt * 16 + h) * 4096 + perm_word(4, r0 + 8, lk)] =
            pk(oacc[di][2], oacc[di][3]);
    }

    rsum[0] += __shfl_xor_sync(0xffffffffu, rsum[0], 1);
    rsum[0] += __shfl_xor_sync(0xffffffffu, rsum[0], 2);
    rsum[1] += __shfl_xor_sync(0xffffffffu, rsum[1], 1);
    rsum[1] += __shfl_xor_sync(0xffffffffu, rsum[1], 2);
    if (t4 == 0) {
        g_rsum[h * SQ + m0 + r0] = rsum[0];
        g_rsum[h * SQ + m0 + r0 + 8] = rsum[1];
    }
}

// ---------------------------------------------------------------------------
// Heterogeneous pass 2: blocks 0..127 = output projection (fp16 cp.async GEMM
// from g_op); blocks 128..383 = recompute S, mask, exp, x inv(rsum), stream
// the NORMALIZED attn once (the only attn traffic in the whole pipeline).
// ---------------------------------------------------------------------------
__global__ __launch_bounds__(256, 2) void pass2(float* __restrict__ C,
                                                float* __restrict__ attn) {
    extern __shared__ uint32_t sm[];
    const int bid = blockIdx.x;
    const int tid = threadIdx.x;
    const int lane = tid & 31, wid = tid >> 5;
    const int g = lane >> 2, t4 = lane & 3;

    if (bid >= 128) {  // attn recompute+normalize: 256 blocks (h, mt)
        const int pb = bid - 128;
        const int h = pb >> 4, mt = pb & 15;
        const int m0 = mt * 128;
        const int r0 = wid * 16 + g;
        const size_t attn_base = (size_t)h * SQ * SQ;
        const uint32_t* kg = g_kp + h * 32 * 2048;
        uint32_t* Qp = sm;         // 4096 w
        uint32_t* Kp = sm + 4096;  // 2 x 2048 w

        {
            const uint32_t* qg = g_qp + (h * 16 + mt) * 4096;
#pragma unroll
            for (int i = 0; i < 4; i++)
                cpa16(Qp + tid * 4 + i * 1024, qg + tid * 4 + i * 1024);
        }
#pragma unroll
        for (int i = 0; i < 2; i++)
            cpa16(Kp + tid * 4 + i * 1024, kg + tid * 4 + i * 1024);
        CPA_COMMIT;
        CPA_WAIT(0);
        __syncthreads();

        uint4 qf[4];
#pragma unroll
        for (int s = 0; s < 4; s++)
            qf[s] = *(const uint4*)&Qp[frag_addr(4, wid, s, g, t4)];

        const float inv0 = 1.0f / g_rsum[h * SQ + m0 + r0];
        const float inv1 = 1.0f / g_rsum[h * SQ + m0 + r0 + 8];

        for (int tt = 0; tt < NT; tt++) {
            const int t0 = tt * 64;
            uint32_t* Kc = Kp + (tt & 1) * 2048;

            uint32_t mw[2][2];
            {
                const uint32_t* mb = g_mbits + (size_t)(tt * 2) * SQ + m0;
                mw[0][0] = mb[r0];
                mw[0][1] = mb[SQ + r0];
                mw[1][0] = mb[r0 + 8];
                mw[1][1] = mb[SQ + r0 + 8];
            }

            if (tt + 1 < NT) {
                uint32_t* Kn = Kp + ((tt + 1) & 1) * 2048;
#pragma unroll
                for (int i = 0; i < 2; i++)
                    cpa16(Kn + tid * 4 + i * 1024,
                          kg + (tt + 1) * 2048 + tid * 4 + i * 1024);
                CPA_COMMIT;
            }

            float sacc[8][4] = {};
#pragma unroll
            for (int s = 0; s < 4; s++) {
#pragma unroll
                for (int b = 0; b < 4; b++) {
                    uint4 bk = *(const uint4*)&Kc[frag_addr(4, b, s, g, t4)];
                    mma16(sacc[b * 2], qf[s].x, qf[s].y, qf[s].z, qf[s].w, bk.x, bk.z);
                    mma16(sacc[b * 2 + 1], qf[s].x, qf[s].y, qf[s].z, qf[s].w, bk.y,
                          bk.w);
                }
            }

#pragma unroll
            for (int ni = 0; ni < 8; ni++) {
                int cl = ni * 8 + 2 * t4;
                int word = ni >> 2, bit = cl & 31;
                float v00 = sacc[ni][0], v01 = sacc[ni][1];
                float v10 = sacc[ni][2], v11 = sacc[ni][3];
                uint32_t w0 = mw[0][word], w1 = mw[1][word];
                if ((w0 >> bit) & 1) v00 = -1e-7f;
                if ((w0 >> (bit + 1)) & 1) v01 = -1e-7f;
                if ((w1 >> bit) & 1) v10 = -1e-7f;
                if ((w1 >> (bit + 1)) & 1) v11 = -1e-7f;
                size_t cg = attn_base + (size_t)(m0 + r0) * SQ + t0 + cl;
                __stcs((float2*)(attn + cg),
                       make_float2(__expf(v00) * inv0, __expf(v01) * inv0));
                __stcs((float2*)(attn + cg + 8 * SQ),
                       make_float2(__expf(v10) * inv1, __expf(v11) * inv1));
            }

            if (tt + 1 < NT) {
                CPA_WAIT(0);
                __syncthreads();
            }
        }
        return;
    }

    // output projection: out = O @ Wo^T from permuted g_op/Wo tiles
    const int mt = bid >> 3, nt = bid & 7;
    const int wm = (wid & 1) * 64, wn = (wid >> 1) * 32;
    const uint32_t* At = g_op + (size_t)(mt * 16) * 4096;
    const uint32_t* Bt = g_wp + (size_t)(3 * 128 + nt * 16) * 4096;

#pragma unroll
    for (int i = 0; i < 4; i++) {
        cpa16(sm + tid * 4 + i * 1024, At + tid * 4 + i * 1024);
        cpa16(sm + 4096 + tid * 4 + i * 1024, Bt + tid * 4 + i * 1024);
    }
    CPA_COMMIT;

    float acc[4][4][4] = {};

    for (int kt = 0; kt < 16; kt++) {
        uint32_t* S = sm + (kt & 1) * 8192;
        CPA_WAIT(0);
        __syncthreads();
        if (kt + 1 < 16) {
            uint32_t* Nx = sm + ((kt + 1) & 1) * 8192;
            const uint32_t* An = At + (kt + 1) * 4096;
            const uint32_t* Bn = Bt + (kt + 1) * 4096;
#pragma unroll
            for (int i = 0; i < 4; i++) {
                cpa16(Nx + tid * 4 + i * 1024, An + tid * 4 + i * 1024);
                cpa16(Nx + 4096 + tid * 4 + i * 1024, Bn + tid * 4 + i * 1024);
            }
            CPA_COMMIT;
        }
#pragma unroll
        for (int s = 0; s < 4; s++) {
            uint4 av[4], bv[2];
#pragma unroll
            for (int mi = 0; mi < 4; mi++)
                av[mi] = *(const uint4*)&S[frag_addr(4, (wm >> 4) + mi, s, g, t4)];
#pragma unroll
            for (int bi = 0; bi < 2; bi++)
                bv[bi] = *(const uint4*)&S[4096 + frag_addr(4, (wn >> 4) + bi, s, g, t4)];
#pragma unroll
            for (int mi = 0; mi < 4; mi++)
#pragma unroll
                for (int bi = 0; bi < 2; bi++) {
                    mma16(acc[mi][bi * 2], av[mi].x, av[mi].y, av[mi].z, av[mi].w,
                          bv[bi].x, bv[bi].z);
                    mma16(acc[mi][bi * 2 + 1], av[mi].x, av[mi].y, av[mi].z, av[mi].w,
                          bv[bi].y, bv[bi].w);
                }
        }
    }

#pragma unroll
    for (int mi = 0; mi < 4; mi++)
#pragma unroll
        for (int ni = 0; ni < 4; ni++)
#pragma unroll
            for (int e = 0; e < 4; e++) {
                int row = mt * 128 + wm + mi * 16 + g + (e >> 1) * 8;
                int col = nt * 128 + wn + ni * 8 + t4 * 2 + (e & 1);
                C[(size_t)row * DM + col] = acc[mi][ni][e];
            }
}

extern "C" void kernel_launch(void* const* d_in, const int* in_sizes, int n_in,
                              void* d_out, int out_size) {
    const float* q_in = (const float*)d_in[0];
    const float* k_in = (const float*)d_in[1];
    const float* v_in = (const float*)d_in[2];
    const int* mask = (const int*)d_in[3];
    const float* Wq = (const float*)d_in[4];
    const float* Wk = (const float*)d_in[5];
    const float* Wv = (const float*)d_in[6];
    const float* Wo = (const float*)d_in[7];

    float* out = (float*)d_out;           // [S, DM]
    float* attn = out + (size_t)SQ * DM;  // [H, S, S]

    static int smem_set = 0;
    if (!smem_set) {
        cudaFuncSetAttribute(fused_pass1, cudaFuncAttributeMaxDynamicSharedMemorySize,
                             49152);
        cudaFuncSetAttribute(gemm_qkv, cudaFuncAttributeMaxDynamicSharedMemorySize,
                             65536);
        cudaFuncSetAttribute(pass2, cudaFuncAttributeMaxDynamicSharedMemorySize,
                             65536);
        smem_set = 1;
    }

    prep<<<1536, 256>>>(q_in, k_in, v_in, Wq, Wk, Wv, Wo, mask);

    dim3 gQKV(8, 16, 3);
    gemm_qkv<<<gQKV, 256, 65536>>>();

    dim3 gFused(SQ / 128, NH, 1);  // (16, 16)
    fused_pass1<<<gFused, 256, 49152>>>();

    pass2<<<128 + 256, 256, 65536>>>(out, attn);
}